// round 5
// baseline (speedup 1.0000x reference)
#include <cuda_runtime.h>
#include <cuda_fp16.h>
#include <math.h>

#define N_NODES 50000
#define N_EDGES 800000
#define IN_DIM 50
#define HID 64
#define HEADS 4
#define NLAYERS 3
#define NC 12
#define INV_SQRT_C 0.25f
#define LN_EPS 1e-5f
#define SCAN_BLK ((N_NODES + 1023) / 1024)   // 49

typedef unsigned long long ull;

__device__ __forceinline__ ull ff2(ull a, ull b, ull c) {
    ull d;
    asm("fma.rn.f32x2 %0, %1, %2, %3;" : "=l"(d) : "l"(a), "l"(b), "l"(c));
    return d;
}
__device__ __forceinline__ ull packf2(float lo, float hi) {
    return ((ull)__float_as_uint(hi) << 32) | (ull)__float_as_uint(lo);
}
__device__ __forceinline__ float sum2(ull v) {
    return __uint_as_float((unsigned)(v & 0xffffffffu)) + __uint_as_float((unsigned)(v >> 32));
}

// ---------------- scratch ----------------------------------------------------
__device__ __align__(16) float  g_h[N_NODES * HID];
__device__ __align__(16) float  g_q[N_NODES * HID];
__device__ __align__(16) float  g_skip[N_NODES * HID];
__device__ __align__(16) __half g_kv[N_NODES * 128];   // per node: 64 k halves + 64 v halves
__device__ int   g_cnt[N_NODES];          // .bss zero; re-zeroed by scan1 each call
__device__ int   g_rowptr[N_NODES + 1];   // LOCAL exclusive scan (block-relative)
__device__ int   g_fill[N_NODES];         // zeroed by hist each call
__device__ ull   g_edge[N_EDGES];         // packed (ea<<32 | src)
__device__ int   g_psum[64];

// ---------------- CSR build (fused) ------------------------------------------
__global__ void k_hist(const int* __restrict__ ei) {
    int e = blockIdx.x * blockDim.x + threadIdx.x;
    if (e < N_NODES) g_fill[e] = 0;
    if (e < N_EDGES) atomicAdd(&g_cnt[ei[N_EDGES + e]], 1);
}

__global__ void k_scan1() {
    __shared__ int wsum[32];
    int t = threadIdx.x, lane = t & 31, wid = t >> 5;
    int i = blockIdx.x * 1024 + t;
    int v = (i < N_NODES) ? g_cnt[i] : 0;
    if (i < N_NODES) g_cnt[i] = 0;        // reset for next replay
    int incl = v;
    #pragma unroll
    for (int o = 1; o < 32; o <<= 1) {
        int u = __shfl_up_sync(0xffffffffu, incl, o);
        if (lane >= o) incl += u;
    }
    if (lane == 31) wsum[wid] = incl;
    __syncthreads();
    if (wid == 0) {
        int ws = wsum[lane];
        int wincl = ws;
        #pragma unroll
        for (int o = 1; o < 32; o <<= 1) {
            int u = __shfl_up_sync(0xffffffffu, wincl, o);
            if (lane >= o) wincl += u;
        }
        wsum[lane] = wincl - ws;
        if (lane == 31) g_psum[blockIdx.x] = wincl;
    }
    __syncthreads();
    int excl = incl - v + wsum[wid];
    if (i < N_NODES) g_rowptr[i] = excl;
}

__global__ void k_scan2() {
    __shared__ int w0tot;
    int t = threadIdx.x, lane = t & 31;
    int v = (t < SCAN_BLK) ? g_psum[t] : 0;
    int incl = v;
    #pragma unroll
    for (int o = 1; o < 32; o <<= 1) {
        int u = __shfl_up_sync(0xffffffffu, incl, o);
        if (lane >= o) incl += u;
    }
    if (t == 31) w0tot = incl;
    __syncthreads();
    int excl = incl - v + ((t >= 32) ? w0tot : 0);
    if (t < SCAN_BLK) g_psum[t] = excl;
    if (t == SCAN_BLK - 1) g_rowptr[N_NODES] = v;   // local count of last block
}

__global__ void k_scatter(const int* __restrict__ ei, const float* __restrict__ ea) {
    int e = blockIdx.x * blockDim.x + threadIdx.x;
    if (e < N_EDGES) {
        int dst = ei[N_EDGES + e];
        int base = g_rowptr[dst] + g_psum[dst >> 10];
        int pos = base + atomicAdd(&g_fill[dst], 1);
        g_edge[pos] = ((ull)__float_as_uint(ea[e]) << 32) | (unsigned)ei[e];
    }
}

// ---------------- input GEMM -------------------------------------------------
__global__ void k_ingemm(const float* __restrict__ x,
                         const float* __restrict__ Win,
                         const float* __restrict__ b_in) {
    __shared__ __align__(16) float xs[64 * 52];
    int c = threadIdx.x;
    ull w2[26];
    #pragma unroll
    for (int k = 0; k < 25; k++)
        w2[k] = packf2(Win[(2 * k) * HID + c], Win[(2 * k + 1) * HID + c]);
    w2[25] = 0ull;
    int n0 = blockIdx.x * 64;
    for (int idx = c; idx < 64 * IN_DIM; idx += 64) {
        int r = idx / IN_DIM, k = idx % IN_DIM;
        int row = n0 + r;
        xs[r * 52 + k] = (row < N_NODES) ? x[row * IN_DIM + k] : 0.f;
    }
    xs[c * 52 + 50] = 0.f;
    xs[c * 52 + 51] = 0.f;
    __syncthreads();
    float bias = b_in[c];
    int rmax = min(64, N_NODES - n0);
    for (int r = 0; r < rmax; r++) {
        const ulonglong2* hr = (const ulonglong2*)&xs[r * 52];
        ull acc_a = packf2(bias, 0.f), acc_b = 0ull;
        #pragma unroll
        for (int kk = 0; kk < 13; kk++) {
            ulonglong2 hv = hr[kk];
            acc_a = ff2(w2[2 * kk + 0], hv.x, acc_a);
            acc_b = ff2(w2[2 * kk + 1], hv.y, acc_b);
        }
        g_h[(n0 + r) * HID + c] = sum2(acc_a) + sum2(acc_b);
    }
}

// ---------------- fused q/k/v/skip GEMM --------------------------------------
__global__ void k_gemm4(int li,
                        const float* __restrict__ Wq, const float* __restrict__ bq,
                        const float* __restrict__ Wk, const float* __restrict__ bk,
                        const float* __restrict__ Wv, const float* __restrict__ bv,
                        const float* __restrict__ Wsk, const float* __restrict__ bsk) {
    __shared__ __align__(16) float hs[64 * 64];
    int t = threadIdx.x;
    int mat = t >> 6, c = t & 63;
    const float* W; const float* b;
    if (mat == 0)      { W = Wq  + li * 4096; b = bq  + li * 64; }
    else if (mat == 1) { W = Wk  + li * 4096; b = bk  + li * 64; }
    else if (mat == 2) { W = Wv  + li * 4096; b = bv  + li * 64; }
    else               { W = Wsk + li * 4096; b = bsk + li * 64; }
    float scal = (mat == 0) ? INV_SQRT_C : 1.f;
    ull w2[32];
    #pragma unroll
    for (int k = 0; k < 32; k++)
        w2[k] = packf2(W[(2 * k) * 64 + c] * scal, W[(2 * k + 1) * 64 + c] * scal);
    float bias = b[c] * scal;
    int n0 = blockIdx.x * 64;
    float4* hs4 = (float4*)hs;
    for (int idx = t; idx < 1024; idx += 256) {
        int row = n0 + (idx >> 4);
        hs4[idx] = (row < N_NODES) ? ((const float4*)g_h)[row * 16 + (idx & 15)]
                                   : make_float4(0.f, 0.f, 0.f, 0.f);
    }
    __syncthreads();
    int rmax = min(64, N_NODES - n0);
    for (int r = 0; r < rmax; r++) {
        const ulonglong2* hr = (const ulonglong2*)&hs[r * 64];
        ull acc_a = packf2(bias, 0.f), acc_b = 0ull;
        #pragma unroll
        for (int kk = 0; kk < 16; kk++) {
            ulonglong2 hv = hr[kk];
            acc_a = ff2(w2[2 * kk + 0], hv.x, acc_a);
            acc_b = ff2(w2[2 * kk + 1], hv.y, acc_b);
        }
        float acc = sum2(acc_a) + sum2(acc_b);
        int n = n0 + r;
        if (mat == 0)      g_q[n * 64 + c] = acc;
        else if (mat == 3) g_skip[n * 64 + c] = acc;
        else               g_kv[n * 128 + ((mat == 2) ? 64 : 0) + c] = __float2half_rn(acc);
    }
}

// ---------------- fused node kernel v3: warp/node, 1 LDG per edge ------------
// lanes 0-15: k channels 4L..4L+3 ; lanes 16-31: v channels 4(L-16)..
__global__ void k_node3(int li,
                        const float* __restrict__ Wedge,
                        const float* __restrict__ Wbeta,
                        const float* __restrict__ lng,
                        const float* __restrict__ lnb) {
    int n = blockIdx.x * (blockDim.x >> 5) + (threadIdx.x >> 5);
    if (n >= N_NODES) return;
    int lane = threadIdx.x & 31;
    int grp = lane & 15;

    float4 q4 = make_float4(0.f, 0.f, 0.f, 0.f);
    if (lane < 16) q4 = ((const float4*)g_q)[n * 16 + lane];   // pre-scaled by 1/4
    float4 we = ((const float4*)Wedge)[li * 16 + grp];

    // per-head dot(q, we), broadcast to all lanes of the head
    float pw = q4.x * we.x + q4.y * we.y + q4.z * we.z + q4.w * we.w;
    pw += __shfl_xor_sync(0xffffffffu, pw, 1, 4);
    pw += __shfl_xor_sync(0xffffffffu, pw, 2, 4);
    float qwe = __shfl_sync(0xffffffffu, pw, lane & 12, 32);

    int j0 = g_rowptr[n] + g_psum[n >> 10];
    int j1 = g_rowptr[n + 1] + g_psum[(n + 1) >> 10];

    float d = 0.f, spw = 0.f;
    float4 acc = make_float4(0.f, 0.f, 0.f, 0.f);

    ull ed = 0; uint2 raw = make_uint2(0u, 0u);
    if (j0 < j1) {
        ed = __ldg(&g_edge[j0]);
        raw = __ldg((const uint2*)g_kv + ((ed & 0xffffffffu) * 32 + lane));
    }
    for (int j = j0; j < j1; j++) {
        ull edc = ed; uint2 rc = raw;
        if (j + 1 < j1) {
            ed = __ldg(&g_edge[j + 1]);
            raw = __ldg((const uint2*)g_kv + ((ed & 0xffffffffu) * 32 + lane));
        }
        float w = __uint_as_float((unsigned)(edc >> 32));
        float2 c01 = __half22float2(*(const __half2*)&rc.x);
        float2 c23 = __half22float2(*(const __half2*)&rc.y);
        float p = q4.x * c01.x + q4.y * c01.y + q4.z * c23.x + q4.w * c23.y;
        p += __shfl_xor_sync(0xffffffffu, p, 1, 4);
        p += __shfl_xor_sync(0xffffffffu, p, 2, 4);
        float ph = __shfl_sync(0xffffffffu, p, lane & 12, 32);  // head dot (k-lanes)
        float ex = __expf(fmaf(w, qwe, ph));                    // shift-invariant
        d += ex;
        spw = fmaf(ex, w, spw);
        acc.x = fmaf(ex, c01.x, acc.x);   // meaningful in v-lanes only
        acc.y = fmaf(ex, c01.y, acc.y);
        acc.z = fmaf(ex, c23.x, acc.z);
        acc.w = fmaf(ex, c23.y, acc.w);
    }

    // epilogue: v-lanes own all 64 channels as float4
    if (lane >= 16) {
        float inv = 1.f / (d + 1e-16f);
        float4 o4;
        o4.x = (acc.x + we.x * spw) * inv;
        o4.y = (acc.y + we.y * spw) * inv;
        o4.z = (acc.z + we.z * spw) * inv;
        o4.w = (acc.w + we.w * spw) * inv;

        float4 xr = ((const float4*)g_skip)[n * 16 + grp];
        const float4* Wb = (const float4*)(Wbeta + li * 192);
        float4 w1 = Wb[grp], w2 = Wb[16 + grp], w3 = Wb[32 + grp];
        float contrib = o4.x * w1.x + o4.y * w1.y + o4.z * w1.z + o4.w * w1.w
                      + xr.x * w2.x + xr.y * w2.y + xr.z * w2.z + xr.w * w2.w
                      + (o4.x - xr.x) * w3.x + (o4.y - xr.y) * w3.y
                      + (o4.z - xr.z) * w3.z + (o4.w - xr.w) * w3.w;
        #pragma unroll
        for (int o = 8; o >= 1; o >>= 1)
            contrib += __shfl_xor_sync(0xffff0000u, contrib, o);
        float beta = 1.f / (1.f + __expf(-contrib));

        float4 hres = ((const float4*)g_h)[n * 16 + grp];
        float4 z;
        z.x = fmaf(beta, xr.x - o4.x, o4.x) + hres.x;
        z.y = fmaf(beta, xr.y - o4.y, o4.y) + hres.y;
        z.z = fmaf(beta, xr.z - o4.z, o4.z) + hres.z;
        z.w = fmaf(beta, xr.w - o4.w, o4.w) + hres.w;

        float s1 = z.x + z.y + z.z + z.w;
        float s2 = z.x * z.x + z.y * z.y + z.z * z.z + z.w * z.w;
        #pragma unroll
        for (int o = 8; o >= 1; o >>= 1) {
            s1 += __shfl_xor_sync(0xffff0000u, s1, o);
            s2 += __shfl_xor_sync(0xffff0000u, s2, o);
        }
        float mu  = s1 * (1.f / 64.f);
        float var = s2 * (1.f / 64.f) - mu * mu;
        float rstd = rsqrtf(var + LN_EPS);
        float4 g = ((const float4*)lng)[li * 16 + grp];
        float4 b = ((const float4*)lnb)[li * 16 + grp];
        float4 hout;
        hout.x = (z.x - mu) * rstd * g.x + b.x;
        hout.y = (z.y - mu) * rstd * g.y + b.y;
        hout.z = (z.z - mu) * rstd * g.z + b.z;
        hout.w = (z.w - mu) * rstd * g.w + b.w;
        ((float4*)g_h)[n * 16 + grp] = hout;
    }
}

// ---------------- head -------------------------------------------------------
__global__ void k_final(const float* __restrict__ Wc1, const float* __restrict__ bc1,
                        const float* __restrict__ Wc2, const float* __restrict__ bc2,
                        float* __restrict__ out) {
    __shared__ __align__(16) float hs[64 * 64];
    __shared__ __align__(16) float h1s[64 * 64];
    int t = threadIdx.x;
    int n0 = blockIdx.x * 64;
    float4* hs4 = (float4*)hs;
    for (int idx = t; idx < 1024; idx += 256) {
        int row = n0 + (idx >> 4);
        hs4[idx] = (row < N_NODES) ? ((const float4*)g_h)[row * 16 + (idx & 15)]
                                   : make_float4(0.f, 0.f, 0.f, 0.f);
    }
    int c = t & 63, rg = t >> 6;
    ull w2[32];
    #pragma unroll
    for (int k = 0; k < 32; k++)
        w2[k] = packf2(Wc1[(2 * k) * 64 + c], Wc1[(2 * k + 1) * 64 + c]);
    float b1 = bc1[c];
    __syncthreads();
    for (int r = rg * 16; r < rg * 16 + 16; r++) {
        const ulonglong2* hr = (const ulonglong2*)&hs[r * 64];
        ull acc_a = packf2(b1, 0.f), acc_b = 0ull;
        #pragma unroll
        for (int kk = 0; kk < 16; kk++) {
            ulonglong2 hv = hr[kk];
            acc_a = ff2(w2[2 * kk + 0], hv.x, acc_a);
            acc_b = ff2(w2[2 * kk + 1], hv.y, acc_b);
        }
        h1s[r * 64 + c] = fmaxf(sum2(acc_a) + sum2(acc_b), 0.f);
    }
    __syncthreads();
    if (t < 240) {
        int c2 = t % 12, rg2 = t / 12;
        ull wr2[32];
        #pragma unroll
        for (int k = 0; k < 32; k++)
            wr2[k] = packf2(Wc2[(2 * k) * NC + c2], Wc2[(2 * k + 1) * NC + c2]);
        float b2 = bc2[c2];
        int rmax = min(64, N_NODES - n0);
        for (int r = rg2; r < rmax; r += 20) {
            const ulonglong2* hr = (const ulonglong2*)&h1s[r * 64];
            ull acc_a = packf2(b2, 0.f), acc_b = 0ull;
            #pragma unroll
            for (int kk = 0; kk < 16; kk++) {
                ulonglong2 hv = hr[kk];
                acc_a = ff2(wr2[2 * kk + 0], hv.x, acc_a);
                acc_b = ff2(wr2[2 * kk + 1], hv.y, acc_b);
            }
            out[(n0 + r) * NC + c2] = sum2(acc_a) + sum2(acc_b);
        }
    }
}

// ---------------- launch -----------------------------------------------------
extern "C" void kernel_launch(void* const* d_in, const int* in_sizes, int n_in,
                              void* d_out, int out_size) {
    const float* x     = (const float*)d_in[0];
    const int*   ei    = (const int*)  d_in[1];
    const float* ea    = (const float*)d_in[2];
    const float* Win   = (const float*)d_in[3];
    const float* b_in  = (const float*)d_in[4];
    const float* Wq    = (const float*)d_in[5];
    const float* bq    = (const float*)d_in[6];
    const float* Wk    = (const float*)d_in[7];
    const float* bk    = (const float*)d_in[8];
    const float* Wv    = (const float*)d_in[9];
    const float* bv    = (const float*)d_in[10];
    const float* Wedge = (const float*)d_in[11];
    const float* Wskip = (const float*)d_in[12];
    const float* bskip = (const float*)d_in[13];
    const float* Wbeta = (const float*)d_in[14];
    const float* ln_g  = (const float*)d_in[15];
    const float* ln_b  = (const float*)d_in[16];
    const float* Wc1   = (const float*)d_in[17];
    const float* bc1   = (const float*)d_in[18];
    const float* Wc2   = (const float*)d_in[19];
    const float* bc2   = (const float*)d_in[20];
    float* out = (float*)d_out;

    int nrb = (N_NODES + 63) / 64;

    k_hist<<<(N_EDGES + 255) / 256, 256>>>(ei);           // 1 (also zeros g_fill)
    k_scan1<<<SCAN_BLK, 1024>>>();                        // 2 (also zeros g_cnt)
    k_scan2<<<1, 64>>>();                                 // 3
    k_ingemm<<<nrb, 64>>>(x, Win, b_in);                  // 4
    k_scatter<<<(N_EDGES + 255) / 256, 256>>>(ei, ea);    // 5

    for (int li = 0; li < NLAYERS; li++) {
        k_gemm4<<<nrb, 256>>>(li, Wq, bq, Wk, bk, Wv, bv, Wskip, bskip);  // 6, 8, 10
        k_node3<<<(N_NODES + 7) / 8, 256>>>(li, Wedge, Wbeta, ln_g, ln_b); // 7, 9, 11
    }

    k_final<<<nrb, 256>>>(Wc1, bc1, Wc2, bc2, out);       // 12
}

// round 6
// speedup vs baseline: 1.0055x; 1.0055x over previous
#include <cuda_runtime.h>
#include <cuda_fp16.h>
#include <math.h>

#define N_NODES 50000
#define N_EDGES 800000
#define IN_DIM 50
#define HID 64
#define HEADS 4
#define NLAYERS 3
#define NC 12
#define INV_SQRT_C 0.25f
#define LN_EPS 1e-5f
#define SCAN_BLK ((N_NODES + 1023) / 1024)   // 49

typedef unsigned long long ull;

__device__ __forceinline__ ull ff2(ull a, ull b, ull c) {
    ull d;
    asm("fma.rn.f32x2 %0, %1, %2, %3;" : "=l"(d) : "l"(a), "l"(b), "l"(c));
    return d;
}
__device__ __forceinline__ ull packf2(float lo, float hi) {
    return ((ull)__float_as_uint(hi) << 32) | (ull)__float_as_uint(lo);
}
__device__ __forceinline__ float sum2(ull v) {
    return __uint_as_float((unsigned)(v & 0xffffffffu)) + __uint_as_float((unsigned)(v >> 32));
}

// ---------------- scratch ----------------------------------------------------
__device__ __align__(16) float  g_h[N_NODES * HID];
__device__ __align__(16) float  g_q[N_NODES * HID];
__device__ __align__(16) float  g_skip[N_NODES * HID];
__device__ __align__(16) __half g_kv[N_NODES * 128];   // per node: 64 k + 64 v halves
__device__ int   g_cnt[N_NODES];          // .bss zero; re-zeroed by scan1 each call
__device__ int   g_rowptr[N_NODES + 1];   // LOCAL exclusive scan (block-relative)
__device__ int   g_fill[N_NODES];         // zeroed by hist each call
__device__ ull   g_edge[N_EDGES];         // packed (ea<<32 | src)
__device__ int   g_psum[64];

// ---------------- CSR build --------------------------------------------------
__global__ void k_hist(const int* __restrict__ ei) {
    int e = blockIdx.x * blockDim.x + threadIdx.x;
    if (e < N_NODES) g_fill[e] = 0;
    if (e < N_EDGES) atomicAdd(&g_cnt[ei[N_EDGES + e]], 1);
}

__global__ void k_scan1() {
    __shared__ int wsum[32];
    int t = threadIdx.x, lane = t & 31, wid = t >> 5;
    int i = blockIdx.x * 1024 + t;
    int v = (i < N_NODES) ? g_cnt[i] : 0;
    if (i < N_NODES) g_cnt[i] = 0;        // reset for next replay
    int incl = v;
    #pragma unroll
    for (int o = 1; o < 32; o <<= 1) {
        int u = __shfl_up_sync(0xffffffffu, incl, o);
        if (lane >= o) incl += u;
    }
    if (lane == 31) wsum[wid] = incl;
    __syncthreads();
    if (wid == 0) {
        int ws = wsum[lane];
        int wincl = ws;
        #pragma unroll
        for (int o = 1; o < 32; o <<= 1) {
            int u = __shfl_up_sync(0xffffffffu, wincl, o);
            if (lane >= o) wincl += u;
        }
        wsum[lane] = wincl - ws;
        if (lane == 31) g_psum[blockIdx.x] = wincl;
    }
    __syncthreads();
    int excl = incl - v + wsum[wid];
    if (i < N_NODES) g_rowptr[i] = excl;
}

__global__ void k_scan2() {
    __shared__ int w0tot;
    int t = threadIdx.x, lane = t & 31;
    int v = (t < SCAN_BLK) ? g_psum[t] : 0;
    int incl = v;
    #pragma unroll
    for (int o = 1; o < 32; o <<= 1) {
        int u = __shfl_up_sync(0xffffffffu, incl, o);
        if (lane >= o) incl += u;
    }
    if (t == 31) w0tot = incl;
    __syncthreads();
    int excl = incl - v + ((t >= 32) ? w0tot : 0);
    if (t < SCAN_BLK) g_psum[t] = excl;
    if (t == SCAN_BLK - 1) g_rowptr[N_NODES] = v;
}

__global__ void k_scatter(const int* __restrict__ ei, const float* __restrict__ ea) {
    int e = blockIdx.x * blockDim.x + threadIdx.x;
    if (e < N_EDGES) {
        int dst = ei[N_EDGES + e];
        int base = g_rowptr[dst] + g_psum[dst >> 10];
        int pos = base + atomicAdd(&g_fill[dst], 1);
        g_edge[pos] = ((ull)__float_as_uint(ea[e]) << 32) | (unsigned)ei[e];
    }
}

// ---------------- input GEMM (256 threads: 4 row-groups x 64 cols) -----------
__global__ void k_ingemm(const float* __restrict__ x,
                         const float* __restrict__ Win,
                         const float* __restrict__ b_in) {
    __shared__ __align__(16) float xs[64 * 52];
    int t = threadIdx.x;
    int c = t & 63, rg = t >> 6;
    ull w2[26];
    #pragma unroll
    for (int k = 0; k < 25; k++)
        w2[k] = packf2(Win[(2 * k) * HID + c], Win[(2 * k + 1) * HID + c]);
    w2[25] = 0ull;
    int n0 = blockIdx.x * 64;
    for (int idx = t; idx < 64 * IN_DIM; idx += 256) {
        int r = idx / IN_DIM, k = idx % IN_DIM;
        int row = n0 + r;
        xs[r * 52 + k] = (row < N_NODES) ? x[row * IN_DIM + k] : 0.f;
    }
    if (rg == 0) { xs[c * 52 + 50] = 0.f; xs[c * 52 + 51] = 0.f; }
    __syncthreads();
    float bias = b_in[c];
    int rend = min(rg * 16 + 16, N_NODES - n0);
    for (int r = rg * 16; r < rend; r++) {
        const ulonglong2* hr = (const ulonglong2*)&xs[r * 52];
        ull acc_a = packf2(bias, 0.f), acc_b = 0ull;
        #pragma unroll
        for (int kk = 0; kk < 13; kk++) {
            ulonglong2 hv = hr[kk];
            acc_a = ff2(w2[2 * kk + 0], hv.x, acc_a);
            acc_b = ff2(w2[2 * kk + 1], hv.y, acc_b);
        }
        g_h[(n0 + r) * HID + c] = sum2(acc_a) + sum2(acc_b);
    }
}

// ---------------- fused q/k/v/skip GEMM --------------------------------------
__global__ void k_gemm4(int li,
                        const float* __restrict__ Wq, const float* __restrict__ bq,
                        const float* __restrict__ Wk, const float* __restrict__ bk,
                        const float* __restrict__ Wv, const float* __restrict__ bv,
                        const float* __restrict__ Wsk, const float* __restrict__ bsk) {
    __shared__ __align__(16) float hs[64 * 64];
    int t = threadIdx.x;
    int mat = t >> 6, c = t & 63;
    const float* W; const float* b;
    if (mat == 0)      { W = Wq  + li * 4096; b = bq  + li * 64; }
    else if (mat == 1) { W = Wk  + li * 4096; b = bk  + li * 64; }
    else if (mat == 2) { W = Wv  + li * 4096; b = bv  + li * 64; }
    else               { W = Wsk + li * 4096; b = bsk + li * 64; }
    float scal = (mat == 0) ? INV_SQRT_C : 1.f;
    ull w2[32];
    #pragma unroll
    for (int k = 0; k < 32; k++)
        w2[k] = packf2(W[(2 * k) * 64 + c] * scal, W[(2 * k + 1) * 64 + c] * scal);
    float bias = b[c] * scal;
    int n0 = blockIdx.x * 64;
    float4* hs4 = (float4*)hs;
    for (int idx = t; idx < 1024; idx += 256) {
        int row = n0 + (idx >> 4);
        hs4[idx] = (row < N_NODES) ? ((const float4*)g_h)[row * 16 + (idx & 15)]
                                   : make_float4(0.f, 0.f, 0.f, 0.f);
    }
    __syncthreads();
    int rmax = min(64, N_NODES - n0);
    for (int r = 0; r < rmax; r++) {
        const ulonglong2* hr = (const ulonglong2*)&hs[r * 64];
        ull acc_a = packf2(bias, 0.f), acc_b = 0ull;
        #pragma unroll
        for (int kk = 0; kk < 16; kk++) {
            ulonglong2 hv = hr[kk];
            acc_a = ff2(w2[2 * kk + 0], hv.x, acc_a);
            acc_b = ff2(w2[2 * kk + 1], hv.y, acc_b);
        }
        float acc = sum2(acc_a) + sum2(acc_b);
        int n = n0 + r;
        if (mat == 0)      g_q[n * 64 + c] = acc;
        else if (mat == 3) g_skip[n * 64 + c] = acc;
        else               g_kv[n * 128 + ((mat == 2) ? 64 : 0) + c] = __float2half_rn(acc);
    }
}

// ---------------- fused node kernel: warp/node, SW pipeline depth 4 ----------
#define LDKV(E) __ldg((const uint2*)g_kv + (((E) & 0xffffffffu) * 32 + lane))
#define NODE_BODY(E, R) { \
    float w_ = __uint_as_float((unsigned)((E) >> 32)); \
    float2 c01_ = __half22float2(*(const __half2*)&(R).x); \
    float2 c23_ = __half22float2(*(const __half2*)&(R).y); \
    float p_ = q4.x * c01_.x + q4.y * c01_.y + q4.z * c23_.x + q4.w * c23_.y; \
    p_ += __shfl_xor_sync(0xffffffffu, p_, 1, 4); \
    p_ += __shfl_xor_sync(0xffffffffu, p_, 2, 4); \
    float ph_ = __shfl_sync(0xffffffffu, p_, lane & 12, 32); \
    float ex_ = __expf(fmaf(w_, qwe, ph_)); \
    d += ex_; spw = fmaf(ex_, w_, spw); \
    acc.x = fmaf(ex_, c01_.x, acc.x); acc.y = fmaf(ex_, c01_.y, acc.y); \
    acc.z = fmaf(ex_, c23_.x, acc.z); acc.w = fmaf(ex_, c23_.y, acc.w); \
}

__global__ void k_node3(int li,
                        const float* __restrict__ Wedge,
                        const float* __restrict__ Wbeta,
                        const float* __restrict__ lng,
                        const float* __restrict__ lnb) {
    int n = blockIdx.x * (blockDim.x >> 5) + (threadIdx.x >> 5);
    if (n >= N_NODES) return;
    int lane = threadIdx.x & 31;
    int grp = lane & 15;

    float4 q4 = make_float4(0.f, 0.f, 0.f, 0.f);
    if (lane < 16) q4 = ((const float4*)g_q)[n * 16 + lane];   // pre-scaled by 1/4
    float4 we = ((const float4*)Wedge)[li * 16 + grp];

    float pw = q4.x * we.x + q4.y * we.y + q4.z * we.z + q4.w * we.w;
    pw += __shfl_xor_sync(0xffffffffu, pw, 1, 4);
    pw += __shfl_xor_sync(0xffffffffu, pw, 2, 4);
    float qwe = __shfl_sync(0xffffffffu, pw, lane & 12, 32);

    int j0 = g_rowptr[n] + g_psum[n >> 10];
    int j1 = g_rowptr[n + 1] + g_psum[(n + 1) >> 10];
    int cnt = j1 - j0;
    const ull* ep = g_edge + j0;

    float d = 0.f, spw = 0.f;
    float4 acc = make_float4(0.f, 0.f, 0.f, 0.f);

    // prologue: fill 4 independent slots (edge -> kv chains overlap, MLP=4)
    ull e0 = 0, e1 = 0, e2 = 0, e3 = 0;
    uint2 r0 = make_uint2(0u,0u), r1 = r0, r2 = r0, r3 = r0;
    if (cnt > 0) { e0 = __ldg(ep + 0); r0 = LDKV(e0); }
    if (cnt > 1) { e1 = __ldg(ep + 1); r1 = LDKV(e1); }
    if (cnt > 2) { e2 = __ldg(ep + 2); r2 = LDKV(e2); }
    if (cnt > 3) { e3 = __ldg(ep + 3); r3 = LDKV(e3); }

    int j = 0;
    for (; j + 8 <= cnt; j += 4) {
        NODE_BODY(e0, r0); e0 = __ldg(ep + j + 4); r0 = LDKV(e0);
        NODE_BODY(e1, r1); e1 = __ldg(ep + j + 5); r1 = LDKV(e1);
        NODE_BODY(e2, r2); e2 = __ldg(ep + j + 6); r2 = LDKV(e2);
        NODE_BODY(e3, r3); e3 = __ldg(ep + j + 7); r3 = LDKV(e3);
    }
    int left = cnt - j;           // 0..7
    if (left > 0) NODE_BODY(e0, r0);
    if (left > 1) NODE_BODY(e1, r1);
    if (left > 2) NODE_BODY(e2, r2);
    if (left > 3) NODE_BODY(e3, r3);
    for (int jj = j + 4; jj < cnt; jj++) {
        ull e = __ldg(ep + jj); uint2 r = LDKV(e);
        NODE_BODY(e, r);
    }

    // epilogue: v-lanes own all 64 channels as float4
    if (lane >= 16) {
        float inv = 1.f / (d + 1e-16f);
        float4 o4;
        o4.x = (acc.x + we.x * spw) * inv;
        o4.y = (acc.y + we.y * spw) * inv;
        o4.z = (acc.z + we.z * spw) * inv;
        o4.w = (acc.w + we.w * spw) * inv;

        float4 xr = ((const float4*)g_skip)[n * 16 + grp];
        const float4* Wb = (const float4*)(Wbeta + li * 192);
        float4 w1 = Wb[grp], w2 = Wb[16 + grp], w3 = Wb[32 + grp];
        float contrib = o4.x * w1.x + o4.y * w1.y + o4.z * w1.z + o4.w * w1.w
                      + xr.x * w2.x + xr.y * w2.y + xr.z * w2.z + xr.w * w2.w
                      + (o4.x - xr.x) * w3.x + (o4.y - xr.y) * w3.y
                      + (o4.z - xr.z) * w3.z + (o4.w - xr.w) * w3.w;
        #pragma unroll
        for (int o = 8; o >= 1; o >>= 1)
            contrib += __shfl_xor_sync(0xffff0000u, contrib, o);
        float beta = 1.f / (1.f + __expf(-contrib));

        float4 hres = ((const float4*)g_h)[n * 16 + grp];
        float4 z;
        z.x = fmaf(beta, xr.x - o4.x, o4.x) + hres.x;
        z.y = fmaf(beta, xr.y - o4.y, o4.y) + hres.y;
        z.z = fmaf(beta, xr.z - o4.z, o4.z) + hres.z;
        z.w = fmaf(beta, xr.w - o4.w, o4.w) + hres.w;

        float s1 = z.x + z.y + z.z + z.w;
        float s2 = z.x * z.x + z.y * z.y + z.z * z.z + z.w * z.w;
        #pragma unroll
        for (int o = 8; o >= 1; o >>= 1) {
            s1 += __shfl_xor_sync(0xffff0000u, s1, o);
            s2 += __shfl_xor_sync(0xffff0000u, s2, o);
        }
        float mu  = s1 * (1.f / 64.f);
        float var = s2 * (1.f / 64.f) - mu * mu;
        float rstd = rsqrtf(var + LN_EPS);
        float4 g = ((const float4*)lng)[li * 16 + grp];
        float4 b = ((const float4*)lnb)[li * 16 + grp];
        float4 hout;
        hout.x = (z.x - mu) * rstd * g.x + b.x;
        hout.y = (z.y - mu) * rstd * g.y + b.y;
        hout.z = (z.z - mu) * rstd * g.z + b.z;
        hout.w = (z.w - mu) * rstd * g.w + b.w;
        ((float4*)g_h)[n * 16 + grp] = hout;
    }
}

// ---------------- head -------------------------------------------------------
__global__ void k_final(const float* __restrict__ Wc1, const float* __restrict__ bc1,
                        const float* __restrict__ Wc2, const float* __restrict__ bc2,
                        float* __restrict__ out) {
    __shared__ __align__(16) float hs[64 * 64];
    __shared__ __align__(16) float h1s[64 * 64];
    int t = threadIdx.x;
    int n0 = blockIdx.x * 64;
    float4* hs4 = (float4*)hs;
    for (int idx = t; idx < 1024; idx += 256) {
        int row = n0 + (idx >> 4);
        hs4[idx] = (row < N_NODES) ? ((const float4*)g_h)[row * 16 + (idx & 15)]
                                   : make_float4(0.f, 0.f, 0.f, 0.f);
    }
    int c = t & 63, rg = t >> 6;
    ull w2[32];
    #pragma unroll
    for (int k = 0; k < 32; k++)
        w2[k] = packf2(Wc1[(2 * k) * 64 + c], Wc1[(2 * k + 1) * 64 + c]);
    float b1 = bc1[c];
    __syncthreads();
    for (int r = rg * 16; r < rg * 16 + 16; r++) {
        const ulonglong2* hr = (const ulonglong2*)&hs[r * 64];
        ull acc_a = packf2(b1, 0.f), acc_b = 0ull;
        #pragma unroll
        for (int kk = 0; kk < 16; kk++) {
            ulonglong2 hv = hr[kk];
            acc_a = ff2(w2[2 * kk + 0], hv.x, acc_a);
            acc_b = ff2(w2[2 * kk + 1], hv.y, acc_b);
        }
        h1s[r * 64 + c] = fmaxf(sum2(acc_a) + sum2(acc_b), 0.f);
    }
    __syncthreads();
    if (t < 240) {
        int c2 = t % 12, rg2 = t / 12;
        ull wr2[32];
        #pragma unroll
        for (int k = 0; k < 32; k++)
            wr2[k] = packf2(Wc2[(2 * k) * NC + c2], Wc2[(2 * k + 1) * NC + c2]);
        float b2 = bc2[c2];
        int rmax = min(64, N_NODES - n0);
        for (int r = rg2; r < rmax; r += 20) {
            const ulonglong2* hr = (const ulonglong2*)&h1s[r * 64];
            ull acc_a = packf2(b2, 0.f), acc_b = 0ull;
            #pragma unroll
            for (int kk = 0; kk < 16; kk++) {
                ulonglong2 hv = hr[kk];
                acc_a = ff2(wr2[2 * kk + 0], hv.x, acc_a);
                acc_b = ff2(wr2[2 * kk + 1], hv.y, acc_b);
            }
            out[(n0 + r) * NC + c2] = sum2(acc_a) + sum2(acc_b);
        }
    }
}

// ---------------- launch -----------------------------------------------------
extern "C" void kernel_launch(void* const* d_in, const int* in_sizes, int n_in,
                              void* d_out, int out_size) {
    const float* x     = (const float*)d_in[0];
    const int*   ei    = (const int*)  d_in[1];
    const float* ea    = (const float*)d_in[2];
    const float* Win   = (const float*)d_in[3];
    const float* b_in  = (const float*)d_in[4];
    const float* Wq    = (const float*)d_in[5];
    const float* bq    = (const float*)d_in[6];
    const float* Wk    = (const float*)d_in[7];
    const float* bk    = (const float*)d_in[8];
    const float* Wv    = (const float*)d_in[9];
    const float* bv    = (const float*)d_in[10];
    const float* Wedge = (const float*)d_in[11];
    const float* Wskip = (const float*)d_in[12];
    const float* bskip = (const float*)d_in[13];
    const float* Wbeta = (const float*)d_in[14];
    const float* ln_g  = (const float*)d_in[15];
    const float* ln_b  = (const float*)d_in[16];
    const float* Wc1   = (const float*)d_in[17];
    const float* bc1   = (const float*)d_in[18];
    const float* Wc2   = (const float*)d_in[19];
    const float* bc2   = (const float*)d_in[20];
    float* out = (float*)d_out;

    int nrb = (N_NODES + 63) / 64;

    // order chosen so launch #4 (ncu capture slot) = k_gemm4
    k_ingemm<<<nrb, 256>>>(x, Win, b_in);                               // 1
    k_hist<<<(N_EDGES + 255) / 256, 256>>>(ei);                         // 2
    k_scan1<<<SCAN_BLK, 1024>>>();                                      // 3
    k_gemm4<<<nrb, 256>>>(0, Wq, bq, Wk, bk, Wv, bv, Wskip, bskip);     // 4 (profiled)
    k_scan2<<<1, 64>>>();                                               // 5
    k_scatter<<<(N_EDGES + 255) / 256, 256>>>(ei, ea);                  // 6
    k_node3<<<(N_NODES + 7) / 8, 256>>>(0, Wedge, Wbeta, ln_g, ln_b);   // 7

    for (int li = 1; li < NLAYERS; li++) {
        k_gemm4<<<nrb, 256>>>(li, Wq, bq, Wk, bk, Wv, bv, Wskip, bskip);
        k_node3<<<(N_NODES + 7) / 8, 256>>>(li, Wedge, Wbeta, ln_g, ln_b);
    }

    k_final<<<nrb, 256>>>(Wc1, bc1, Wc2, bc2, out);
}

// round 7
// speedup vs baseline: 1.2761x; 1.2691x over previous
#include <cuda_runtime.h>
#include <cuda_fp16.h>
#include <math.h>

#define N_NODES 50000
#define N_EDGES 800000
#define IN_DIM 50
#define HID 64
#define HEADS 4
#define NLAYERS 3
#define NC 12
#define INV_SQRT_C 0.25f
#define LN_EPS 1e-5f
#define SCAN_BLK ((N_NODES + 1023) / 1024)   // 49

typedef unsigned long long ull;

__device__ __forceinline__ ull ff2(ull a, ull b, ull c) {
    ull d;
    asm("fma.rn.f32x2 %0, %1, %2, %3;" : "=l"(d) : "l"(a), "l"(b), "l"(c));
    return d;
}
__device__ __forceinline__ ull packf2(float lo, float hi) {
    return ((ull)__float_as_uint(hi) << 32) | (ull)__float_as_uint(lo);
}
__device__ __forceinline__ float sum2(ull v) {
    return __uint_as_float((unsigned)(v & 0xffffffffu)) + __uint_as_float((unsigned)(v >> 32));
}

// ---------------- scratch ----------------------------------------------------
__device__ __align__(16) float  g_h[N_NODES * HID];
__device__ __align__(16) float  g_q[N_NODES * HID];
__device__ __align__(16) float  g_skip[N_NODES * HID];
__device__ __align__(16) __half g_kv[N_NODES * 128];   // per node: 64 k + 64 v halves
__device__ int   g_cnt[N_NODES];
__device__ int   g_rowptr[N_NODES + 1];
__device__ int   g_fill[N_NODES];
__device__ ull   g_edge[N_EDGES];
__device__ int   g_psum[64];

// ---------------- CSR build --------------------------------------------------
__global__ void k_hist(const int* __restrict__ ei) {
    int e = blockIdx.x * blockDim.x + threadIdx.x;
    if (e < N_NODES) g_fill[e] = 0;
    if (e < N_EDGES) atomicAdd(&g_cnt[ei[N_EDGES + e]], 1);
}

__global__ void k_scan1() {
    __shared__ int wsum[32];
    int t = threadIdx.x, lane = t & 31, wid = t >> 5;
    int i = blockIdx.x * 1024 + t;
    int v = (i < N_NODES) ? g_cnt[i] : 0;
    if (i < N_NODES) g_cnt[i] = 0;
    int incl = v;
    #pragma unroll
    for (int o = 1; o < 32; o <<= 1) {
        int u = __shfl_up_sync(0xffffffffu, incl, o);
        if (lane >= o) incl += u;
    }
    if (lane == 31) wsum[wid] = incl;
    __syncthreads();
    if (wid == 0) {
        int ws = wsum[lane];
        int wincl = ws;
        #pragma unroll
        for (int o = 1; o < 32; o <<= 1) {
            int u = __shfl_up_sync(0xffffffffu, wincl, o);
            if (lane >= o) wincl += u;
        }
        wsum[lane] = wincl - ws;
        if (lane == 31) g_psum[blockIdx.x] = wincl;
    }
    __syncthreads();
    int excl = incl - v + wsum[wid];
    if (i < N_NODES) g_rowptr[i] = excl;
}

__global__ void k_scan2() {
    __shared__ int w0tot;
    int t = threadIdx.x, lane = t & 31;
    int v = (t < SCAN_BLK) ? g_psum[t] : 0;
    int incl = v;
    #pragma unroll
    for (int o = 1; o < 32; o <<= 1) {
        int u = __shfl_up_sync(0xffffffffu, incl, o);
        if (lane >= o) incl += u;
    }
    if (t == 31) w0tot = incl;
    __syncthreads();
    int excl = incl - v + ((t >= 32) ? w0tot : 0);
    if (t < SCAN_BLK) g_psum[t] = excl;
    if (t == SCAN_BLK - 1) g_rowptr[N_NODES] = v;
}

__global__ void k_scatter(const int* __restrict__ ei, const float* __restrict__ ea) {
    int e = blockIdx.x * blockDim.x + threadIdx.x;
    if (e < N_EDGES) {
        int dst = ei[N_EDGES + e];
        int base = g_rowptr[dst] + g_psum[dst >> 10];
        int pos = base + atomicAdd(&g_fill[dst], 1);
        g_edge[pos] = ((ull)__float_as_uint(ea[e]) << 32) | (unsigned)ei[e];
    }
}

// ---------------- input GEMM -------------------------------------------------
__global__ void k_ingemm(const float* __restrict__ x,
                         const float* __restrict__ Win,
                         const float* __restrict__ b_in) {
    __shared__ __align__(16) float xs[64 * 52];
    int t = threadIdx.x;
    int c = t & 63, rg = t >> 6;
    ull w2[26];
    #pragma unroll
    for (int k = 0; k < 25; k++)
        w2[k] = packf2(Win[(2 * k) * HID + c], Win[(2 * k + 1) * HID + c]);
    w2[25] = 0ull;
    int n0 = blockIdx.x * 64;
    for (int idx = t; idx < 64 * IN_DIM; idx += 256) {
        int r = idx / IN_DIM, k = idx % IN_DIM;
        int row = n0 + r;
        xs[r * 52 + k] = (row < N_NODES) ? x[row * IN_DIM + k] : 0.f;
    }
    if (rg == 0) { xs[c * 52 + 50] = 0.f; xs[c * 52 + 51] = 0.f; }
    __syncthreads();
    float bias = b_in[c];
    int rend = min(rg * 16 + 16, N_NODES - n0);
    for (int r = rg * 16; r < rend; r++) {
        const ulonglong2* hr = (const ulonglong2*)&xs[r * 52];
        ull acc_a = packf2(bias, 0.f), acc_b = 0ull;
        #pragma unroll
        for (int kk = 0; kk < 13; kk++) {
            ulonglong2 hv = hr[kk];
            acc_a = ff2(w2[2 * kk + 0], hv.x, acc_a);
            acc_b = ff2(w2[2 * kk + 1], hv.y, acc_b);
        }
        g_h[(n0 + r) * HID + c] = sum2(acc_a) + sum2(acc_b);
    }
}

// ---------------- q/k/v/skip GEMM via tensor cores (m16n8k16 HMMA) ----------
// 512 threads = 16 warps: warp w -> mat = w&3, rowgroup rg = w>>2 (16 rows)
__global__ __launch_bounds__(512) void k_gemm4(int li,
                        const float* __restrict__ Wq, const float* __restrict__ bq,
                        const float* __restrict__ Wk, const float* __restrict__ bk,
                        const float* __restrict__ Wv, const float* __restrict__ bv,
                        const float* __restrict__ Wsk, const float* __restrict__ bsk) {
    __shared__ __half As[64][72];          // h tile fp16, padded stride
    __shared__ __half Bs[4][64][72];       // Bs[mat][n][k] = W[k][n] (scaled)
    __shared__ float  bias_s[4][64];

    int t = threadIdx.x;
    int w = t >> 5, lane = t & 31;
    int mat = w & 3, rg = w >> 2;
    int n0 = blockIdx.x * 64;

    const float* W; const float* b;
    if (mat == 0)      { W = Wq  + li * 4096; b = bq  + li * 64; }
    else if (mat == 1) { W = Wk  + li * 4096; b = bk  + li * 64; }
    else if (mat == 2) { W = Wv  + li * 4096; b = bv  + li * 64; }
    else               { W = Wsk + li * 4096; b = bsk + li * 64; }
    float scal = (mat == 0) ? INV_SQRT_C : 1.f;

    // stage h tile -> fp16 (coalesced)
    for (int idx = t; idx < 64 * 64; idx += 512) {
        int r = idx >> 6, k = idx & 63;
        int row = n0 + r;
        As[r][k] = __float2half_rn((row < N_NODES) ? g_h[row * 64 + k] : 0.f);
    }
    // stage weights transposed (coalesced over n)
    for (int idx = rg * 32 + lane; idx < 4096; idx += 128) {
        int k = idx >> 6, n = idx & 63;
        Bs[mat][n][k] = __float2half_rn(W[k * 64 + n] * scal);
    }
    if (rg == 0)
        for (int c = lane; c < 64; c += 32) bias_s[mat][c] = b[c] * scal;
    __syncthreads();

    int g = lane >> 2, tig = lane & 3;
    int r0 = rg * 16;

    // A fragments per k-step (reused across all 8 n-tiles)
    unsigned afr[4][4];
    #pragma unroll
    for (int ks = 0; ks < 4; ks++) {
        int k0 = ks * 16;
        afr[ks][0] = *(const unsigned*)&As[r0 + g][k0 + 2 * tig];
        afr[ks][1] = *(const unsigned*)&As[r0 + g + 8][k0 + 2 * tig];
        afr[ks][2] = *(const unsigned*)&As[r0 + g][k0 + 2 * tig + 8];
        afr[ks][3] = *(const unsigned*)&As[r0 + g + 8][k0 + 2 * tig + 8];
    }

    int row0 = n0 + r0 + g;
    int row1 = row0 + 8;

    #pragma unroll
    for (int nt = 0; nt < 8; nt++) {
        int col = nt * 8 + 2 * tig;
        float c0 = bias_s[mat][col], c1 = bias_s[mat][col + 1];
        float c2 = c0, c3 = c1;
        #pragma unroll
        for (int ks = 0; ks < 4; ks++) {
            unsigned b0 = *(const unsigned*)&Bs[mat][nt * 8 + g][ks * 16 + 2 * tig];
            unsigned b1 = *(const unsigned*)&Bs[mat][nt * 8 + g][ks * 16 + 2 * tig + 8];
            asm volatile(
                "mma.sync.aligned.m16n8k16.row.col.f32.f16.f16.f32 "
                "{%0,%1,%2,%3}, {%4,%5,%6,%7}, {%8,%9}, {%0,%1,%2,%3};"
                : "+f"(c0), "+f"(c1), "+f"(c2), "+f"(c3)
                : "r"(afr[ks][0]), "r"(afr[ks][1]), "r"(afr[ks][2]), "r"(afr[ks][3]),
                  "r"(b0), "r"(b1));
        }
        if (mat == 0) {
            if (row0 < N_NODES) *(float2*)&g_q[row0 * 64 + col] = make_float2(c0, c1);
            if (row1 < N_NODES) *(float2*)&g_q[row1 * 64 + col] = make_float2(c2, c3);
        } else if (mat == 3) {
            if (row0 < N_NODES) *(float2*)&g_skip[row0 * 64 + col] = make_float2(c0, c1);
            if (row1 < N_NODES) *(float2*)&g_skip[row1 * 64 + col] = make_float2(c2, c3);
        } else {
            int off = (mat == 2) ? 64 : 0;
            if (row0 < N_NODES) *(__half2*)&g_kv[row0 * 128 + off + col] = __floats2half2_rn(c0, c1);
            if (row1 < N_NODES) *(__half2*)&g_kv[row1 * 128 + off + col] = __floats2half2_rn(c2, c3);
        }
    }
}

// ---------------- fused node kernel: warp/node, SW pipeline depth 4 ----------
#define LDKV(E) __ldg((const uint2*)g_kv + (((E) & 0xffffffffu) * 32 + lane))
#define NODE_BODY(E, R) { \
    float w_ = __uint_as_float((unsigned)((E) >> 32)); \
    float2 c01_ = __half22float2(*(const __half2*)&(R).x); \
    float2 c23_ = __half22float2(*(const __half2*)&(R).y); \
    float p_ = q4.x * c01_.x + q4.y * c01_.y + q4.z * c23_.x + q4.w * c23_.y; \
    p_ += __shfl_xor_sync(0xffffffffu, p_, 1, 4); \
    p_ += __shfl_xor_sync(0xffffffffu, p_, 2, 4); \
    float ph_ = __shfl_sync(0xffffffffu, p_, lane & 12, 32); \
    float ex_ = __expf(fmaf(w_, qwe, ph_)); \
    d += ex_; spw = fmaf(ex_, w_, spw); \
    acc.x = fmaf(ex_, c01_.x, acc.x); acc.y = fmaf(ex_, c01_.y, acc.y); \
    acc.z = fmaf(ex_, c23_.x, acc.z); acc.w = fmaf(ex_, c23_.y, acc.w); \
}

__global__ void k_node3(int li,
                        const float* __restrict__ Wedge,
                        const float* __restrict__ Wbeta,
                        const float* __restrict__ lng,
                        const float* __restrict__ lnb) {
    int n = blockIdx.x * (blockDim.x >> 5) + (threadIdx.x >> 5);
    if (n >= N_NODES) return;
    int lane = threadIdx.x & 31;
    int grp = lane & 15;

    float4 q4 = make_float4(0.f, 0.f, 0.f, 0.f);
    if (lane < 16) q4 = ((const float4*)g_q)[n * 16 + lane];
    float4 we = ((const float4*)Wedge)[li * 16 + grp];

    float pw = q4.x * we.x + q4.y * we.y + q4.z * we.z + q4.w * we.w;
    pw += __shfl_xor_sync(0xffffffffu, pw, 1, 4);
    pw += __shfl_xor_sync(0xffffffffu, pw, 2, 4);
    float qwe = __shfl_sync(0xffffffffu, pw, lane & 12, 32);

    int j0 = g_rowptr[n] + g_psum[n >> 10];
    int j1 = g_rowptr[n + 1] + g_psum[(n + 1) >> 10];
    int cnt = j1 - j0;
    const ull* ep = g_edge + j0;

    float d = 0.f, spw = 0.f;
    float4 acc = make_float4(0.f, 0.f, 0.f, 0.f);

    ull e0 = 0, e1 = 0, e2 = 0, e3 = 0;
    uint2 r0 = make_uint2(0u,0u), r1 = r0, r2 = r0, r3 = r0;
    if (cnt > 0) { e0 = __ldg(ep + 0); r0 = LDKV(e0); }
    if (cnt > 1) { e1 = __ldg(ep + 1); r1 = LDKV(e1); }
    if (cnt > 2) { e2 = __ldg(ep + 2); r2 = LDKV(e2); }
    if (cnt > 3) { e3 = __ldg(ep + 3); r3 = LDKV(e3); }

    int j = 0;
    for (; j + 8 <= cnt; j += 4) {
        NODE_BODY(e0, r0); e0 = __ldg(ep + j + 4); r0 = LDKV(e0);
        NODE_BODY(e1, r1); e1 = __ldg(ep + j + 5); r1 = LDKV(e1);
        NODE_BODY(e2, r2); e2 = __ldg(ep + j + 6); r2 = LDKV(e2);
        NODE_BODY(e3, r3); e3 = __ldg(ep + j + 7); r3 = LDKV(e3);
    }
    int left = cnt - j;
    if (left > 0) NODE_BODY(e0, r0);
    if (left > 1) NODE_BODY(e1, r1);
    if (left > 2) NODE_BODY(e2, r2);
    if (left > 3) NODE_BODY(e3, r3);
    for (int jj = j + 4; jj < cnt; jj++) {
        ull e = __ldg(ep + jj); uint2 r = LDKV(e);
        NODE_BODY(e, r);
    }

    if (lane >= 16) {
        float inv = 1.f / (d + 1e-16f);
        float4 o4;
        o4.x = (acc.x + we.x * spw) * inv;
        o4.y = (acc.y + we.y * spw) * inv;
        o4.z = (acc.z + we.z * spw) * inv;
        o4.w = (acc.w + we.w * spw) * inv;

        float4 xr = ((const float4*)g_skip)[n * 16 + grp];
        const float4* Wb = (const float4*)(Wbeta + li * 192);
        float4 w1 = Wb[grp], w2 = Wb[16 + grp], w3 = Wb[32 + grp];
        float contrib = o4.x * w1.x + o4.y * w1.y + o4.z * w1.z + o4.w * w1.w
                      + xr.x * w2.x + xr.y * w2.y + xr.z * w2.z + xr.w * w2.w
                      + (o4.x - xr.x) * w3.x + (o4.y - xr.y) * w3.y
                      + (o4.z - xr.z) * w3.z + (o4.w - xr.w) * w3.w;
        #pragma unroll
        for (int o = 8; o >= 1; o >>= 1)
            contrib += __shfl_xor_sync(0xffff0000u, contrib, o);
        float beta = 1.f / (1.f + __expf(-contrib));

        float4 hres = ((const float4*)g_h)[n * 16 + grp];
        float4 z;
        z.x = fmaf(beta, xr.x - o4.x, o4.x) + hres.x;
        z.y = fmaf(beta, xr.y - o4.y, o4.y) + hres.y;
        z.z = fmaf(beta, xr.z - o4.z, o4.z) + hres.z;
        z.w = fmaf(beta, xr.w - o4.w, o4.w) + hres.w;

        float s1 = z.x + z.y + z.z + z.w;
        float s2 = z.x * z.x + z.y * z.y + z.z * z.z + z.w * z.w;
        #pragma unroll
        for (int o = 8; o >= 1; o >>= 1) {
            s1 += __shfl_xor_sync(0xffff0000u, s1, o);
            s2 += __shfl_xor_sync(0xffff0000u, s2, o);
        }
        float mu  = s1 * (1.f / 64.f);
        float var = s2 * (1.f / 64.f) - mu * mu;
        float rstd = rsqrtf(var + LN_EPS);
        float4 g = ((const float4*)lng)[li * 16 + grp];
        float4 b = ((const float4*)lnb)[li * 16 + grp];
        float4 hout;
        hout.x = (z.x - mu) * rstd * g.x + b.x;
        hout.y = (z.y - mu) * rstd * g.y + b.y;
        hout.z = (z.z - mu) * rstd * g.z + b.z;
        hout.w = (z.w - mu) * rstd * g.w + b.w;
        ((float4*)g_h)[n * 16 + grp] = hout;
    }
}

// ---------------- head -------------------------------------------------------
__global__ void k_final(const float* __restrict__ Wc1, const float* __restrict__ bc1,
                        const float* __restrict__ Wc2, const float* __restrict__ bc2,
                        float* __restrict__ out) {
    __shared__ __align__(16) float hs[64 * 64];
    __shared__ __align__(16) float h1s[64 * 64];
    int t = threadIdx.x;
    int n0 = blockIdx.x * 64;
    float4* hs4 = (float4*)hs;
    for (int idx = t; idx < 1024; idx += 256) {
        int row = n0 + (idx >> 4);
        hs4[idx] = (row < N_NODES) ? ((const float4*)g_h)[row * 16 + (idx & 15)]
                                   : make_float4(0.f, 0.f, 0.f, 0.f);
    }
    int c = t & 63, rg = t >> 6;
    ull w2[32];
    #pragma unroll
    for (int k = 0; k < 32; k++)
        w2[k] = packf2(Wc1[(2 * k) * 64 + c], Wc1[(2 * k + 1) * 64 + c]);
    float b1 = bc1[c];
    __syncthreads();
    for (int r = rg * 16; r < rg * 16 + 16; r++) {
        const ulonglong2* hr = (const ulonglong2*)&hs[r * 64];
        ull acc_a = packf2(b1, 0.f), acc_b = 0ull;
        #pragma unroll
        for (int kk = 0; kk < 16; kk++) {
            ulonglong2 hv = hr[kk];
            acc_a = ff2(w2[2 * kk + 0], hv.x, acc_a);
            acc_b = ff2(w2[2 * kk + 1], hv.y, acc_b);
        }
        h1s[r * 64 + c] = fmaxf(sum2(acc_a) + sum2(acc_b), 0.f);
    }
    __syncthreads();
    if (t < 240) {
        int c2 = t % 12, rg2 = t / 12;
        ull wr2[32];
        #pragma unroll
        for (int k = 0; k < 32; k++)
            wr2[k] = packf2(Wc2[(2 * k) * NC + c2], Wc2[(2 * k + 1) * NC + c2]);
        float b2 = bc2[c2];
        int rmax = min(64, N_NODES - n0);
        for (int r = rg2; r < rmax; r += 20) {
            const ulonglong2* hr = (const ulonglong2*)&h1s[r * 64];
            ull acc_a = packf2(b2, 0.f), acc_b = 0ull;
            #pragma unroll
            for (int kk = 0; kk < 16; kk++) {
                ulonglong2 hv = hr[kk];
                acc_a = ff2(wr2[2 * kk + 0], hv.x, acc_a);
                acc_b = ff2(wr2[2 * kk + 1], hv.y, acc_b);
            }
            out[(n0 + r) * NC + c2] = sum2(acc_a) + sum2(acc_b);
        }
    }
}

// ---------------- launch -----------------------------------------------------
extern "C" void kernel_launch(void* const* d_in, const int* in_sizes, int n_in,
                              void* d_out, int out_size) {
    const float* x     = (const float*)d_in[0];
    const int*   ei    = (const int*)  d_in[1];
    const float* ea    = (const float*)d_in[2];
    const float* Win   = (const float*)d_in[3];
    const float* b_in  = (const float*)d_in[4];
    const float* Wq    = (const float*)d_in[5];
    const float* bq    = (const float*)d_in[6];
    const float* Wk    = (const float*)d_in[7];
    const float* bk    = (const float*)d_in[8];
    const float* Wv    = (const float*)d_in[9];
    const float* bv    = (const float*)d_in[10];
    const float* Wedge = (const float*)d_in[11];
    const float* Wskip = (const float*)d_in[12];
    const float* bskip = (const float*)d_in[13];
    const float* Wbeta = (const float*)d_in[14];
    const float* ln_g  = (const float*)d_in[15];
    const float* ln_b  = (const float*)d_in[16];
    const float* Wc1   = (const float*)d_in[17];
    const float* bc1   = (const float*)d_in[18];
    const float* Wc2   = (const float*)d_in[19];
    const float* bc2   = (const float*)d_in[20];
    float* out = (float*)d_out;

    int nrb = (N_NODES + 63) / 64;

    // launch #4 = k_gemm4 (ncu capture slot)
    k_ingemm<<<nrb, 256>>>(x, Win, b_in);                               // 1
    k_hist<<<(N_EDGES + 255) / 256, 256>>>(ei);                         // 2
    k_scan1<<<SCAN_BLK, 1024>>>();                                      // 3
    k_gemm4<<<nrb, 512>>>(0, Wq, bq, Wk, bk, Wv, bv, Wskip, bskip);     // 4 (profiled)
    k_scan2<<<1, 64>>>();                                               // 5
    k_scatter<<<(N_EDGES + 255) / 256, 256>>>(ei, ea);                  // 6
    k_node3<<<(N_NODES + 7) / 8, 256>>>(0, Wedge, Wbeta, ln_g, ln_b);   // 7

    for (int li = 1; li < NLAYERS; li++) {
        k_gemm4<<<nrb, 512>>>(li, Wq, bq, Wk, bk, Wv, bv, Wskip, bskip);
        k_node3<<<(N_NODES + 7) / 8, 256>>>(li, Wedge, Wbeta, ln_g, ln_b);
    }

    k_final<<<nrb, 256>>>(Wc1, bc1, Wc2, bc2, out);
}

// round 8
// speedup vs baseline: 1.3217x; 1.0357x over previous
#include <cuda_runtime.h>
#include <cuda_fp16.h>
#include <math.h>

#define N_NODES 50000
#define N_EDGES 800000
#define IN_DIM 50
#define HID 64
#define HEADS 4
#define NLAYERS 3
#define NC 12
#define INV_SQRT_C 0.25f
#define LN_EPS 1e-5f
#define SCAN_BLK ((N_NODES + 1023) / 1024)   // 49

typedef unsigned long long ull;

__device__ __forceinline__ ull ff2(ull a, ull b, ull c) {
    ull d;
    asm("fma.rn.f32x2 %0, %1, %2, %3;" : "=l"(d) : "l"(a), "l"(b), "l"(c));
    return d;
}
__device__ __forceinline__ ull packf2(float lo, float hi) {
    return ((ull)__float_as_uint(hi) << 32) | (ull)__float_as_uint(lo);
}
__device__ __forceinline__ float sum2(ull v) {
    return __uint_as_float((unsigned)(v & 0xffffffffu)) + __uint_as_float((unsigned)(v >> 32));
}

// ---------------- scratch ----------------------------------------------------
__device__ __align__(16) float  g_h[N_NODES * HID];
__device__ __align__(16) float  g_q[N_NODES * HID];
__device__ __align__(16) float  g_skip[N_NODES * HID];
__device__ __align__(16) __half g_kv[N_NODES * 128];   // per node: 64 k + 64 v halves
__device__ __align__(16) __half g_wt[12 * 64 * 72];    // [li*4+mat][n][72] fp16 W^T (scaled)
__device__ int   g_cnt[N_NODES];
__device__ int   g_rowptr[N_NODES + 1];
__device__ int   g_fill[N_NODES];
__device__ ull   g_edge[N_EDGES];
__device__ int   g_psum[64];

// ---------------- weight precompute: fp16, transposed, padded, scaled --------
__global__ void k_prep_w(const float* __restrict__ Wq, const float* __restrict__ Wk,
                         const float* __restrict__ Wv, const float* __restrict__ Wsk) {
    int id = blockIdx.x * blockDim.x + threadIdx.x;   // 12*64*64 total
    if (id >= 12 * 4096) return;
    int k = id & 63, n = (id >> 6) & 63, m = id >> 12;
    int li = m >> 2, mat = m & 3;
    const float* W;
    if (mat == 0)      W = Wq  + li * 4096;
    else if (mat == 1) W = Wk  + li * 4096;
    else if (mat == 2) W = Wv  + li * 4096;
    else               W = Wsk + li * 4096;
    float scal = (mat == 0) ? INV_SQRT_C : 1.f;
    g_wt[(m * 64 + n) * 72 + k] = __float2half_rn(W[k * 64 + n] * scal);
}

// ---------------- CSR build --------------------------------------------------
__global__ void k_hist(const int* __restrict__ ei) {
    int e = blockIdx.x * blockDim.x + threadIdx.x;
    if (e < N_NODES) g_fill[e] = 0;
    if (e < N_EDGES) atomicAdd(&g_cnt[ei[N_EDGES + e]], 1);
}

__global__ void k_scan1() {
    __shared__ int wsum[32];
    int t = threadIdx.x, lane = t & 31, wid = t >> 5;
    int i = blockIdx.x * 1024 + t;
    int v = (i < N_NODES) ? g_cnt[i] : 0;
    if (i < N_NODES) g_cnt[i] = 0;
    int incl = v;
    #pragma unroll
    for (int o = 1; o < 32; o <<= 1) {
        int u = __shfl_up_sync(0xffffffffu, incl, o);
        if (lane >= o) incl += u;
    }
    if (lane == 31) wsum[wid] = incl;
    __syncthreads();
    if (wid == 0) {
        int ws = wsum[lane];
        int wincl = ws;
        #pragma unroll
        for (int o = 1; o < 32; o <<= 1) {
            int u = __shfl_up_sync(0xffffffffu, wincl, o);
            if (lane >= o) wincl += u;
        }
        wsum[lane] = wincl - ws;
        if (lane == 31) g_psum[blockIdx.x] = wincl;
    }
    __syncthreads();
    int excl = incl - v + wsum[wid];
    if (i < N_NODES) g_rowptr[i] = excl;
}

__global__ void k_scan2() {
    __shared__ int w0tot;
    int t = threadIdx.x, lane = t & 31;
    int v = (t < SCAN_BLK) ? g_psum[t] : 0;
    int incl = v;
    #pragma unroll
    for (int o = 1; o < 32; o <<= 1) {
        int u = __shfl_up_sync(0xffffffffu, incl, o);
        if (lane >= o) incl += u;
    }
    if (t == 31) w0tot = incl;
    __syncthreads();
    int excl = incl - v + ((t >= 32) ? w0tot : 0);
    if (t < SCAN_BLK) g_psum[t] = excl;
    if (t == SCAN_BLK - 1) g_rowptr[N_NODES] = v;
}

__global__ void k_scatter(const int* __restrict__ ei, const float* __restrict__ ea) {
    int e = blockIdx.x * blockDim.x + threadIdx.x;
    if (e < N_EDGES) {
        int dst = ei[N_EDGES + e];
        int base = g_rowptr[dst] + g_psum[dst >> 10];
        int pos = base + atomicAdd(&g_fill[dst], 1);
        g_edge[pos] = ((ull)__float_as_uint(ea[e]) << 32) | (unsigned)ei[e];
    }
}

// ---------------- input GEMM -------------------------------------------------
__global__ void k_ingemm(const float* __restrict__ x,
                         const float* __restrict__ Win,
                         const float* __restrict__ b_in) {
    __shared__ __align__(16) float xs[64 * 52];
    int t = threadIdx.x;
    int c = t & 63, rg = t >> 6;
    ull w2[26];
    #pragma unroll
    for (int k = 0; k < 25; k++)
        w2[k] = packf2(Win[(2 * k) * HID + c], Win[(2 * k + 1) * HID + c]);
    w2[25] = 0ull;
    int n0 = blockIdx.x * 64;
    for (int idx = t; idx < 64 * IN_DIM; idx += 256) {
        int r = idx / IN_DIM, k = idx % IN_DIM;
        int row = n0 + r;
        xs[r * 52 + k] = (row < N_NODES) ? x[row * IN_DIM + k] : 0.f;
    }
    if (rg == 0) { xs[c * 52 + 50] = 0.f; xs[c * 52 + 51] = 0.f; }
    __syncthreads();
    float bias = b_in[c];
    int rend = min(rg * 16 + 16, N_NODES - n0);
    for (int r = rg * 16; r < rend; r++) {
        const ulonglong2* hr = (const ulonglong2*)&xs[r * 52];
        ull acc_a = packf2(bias, 0.f), acc_b = 0ull;
        #pragma unroll
        for (int kk = 0; kk < 13; kk++) {
            ulonglong2 hv = hr[kk];
            acc_a = ff2(w2[2 * kk + 0], hv.x, acc_a);
            acc_b = ff2(w2[2 * kk + 1], hv.y, acc_b);
        }
        g_h[(n0 + r) * HID + c] = sum2(acc_a) + sum2(acc_b);
    }
}

// ---------------- q/k/v/skip GEMM via tensor cores (m16n8k16 HMMA) ----------
// 512 threads = 16 warps: warp w -> mat = w&3, rowgroup rg = w>>2 (16 rows)
__global__ __launch_bounds__(512) void k_gemm4(int li,
                        const float* __restrict__ bq, const float* __restrict__ bk,
                        const float* __restrict__ bv, const float* __restrict__ bsk) {
    __shared__ __half As[64][72];          // h tile fp16, padded stride
    __shared__ __half Bs[4][64][72];       // pre-transposed fp16 weights
    __shared__ float  bias_s[4][64];

    int t = threadIdx.x;
    int w = t >> 5, lane = t & 31;
    int mat = w & 3, rg = w >> 2;
    int n0 = blockIdx.x * 64;

    const float* b;
    if (mat == 0)      b = bq  + li * 64;
    else if (mat == 1) b = bk  + li * 64;
    else if (mat == 2) b = bv  + li * 64;
    else               b = bsk + li * 64;
    float scal = (mat == 0) ? INV_SQRT_C : 1.f;

    // stage h tile -> fp16 (coalesced)
    for (int idx = t; idx < 64 * 64; idx += 512) {
        int r = idx >> 6, k = idx & 63;
        int row = n0 + r;
        As[r][k] = __float2half_rn((row < N_NODES) ? g_h[row * 64 + k] : 0.f);
    }
    // copy precomputed fp16 weights (coalesced uint4, layout-identical)
    {
        const uint4* src = (const uint4*)(g_wt + (li * 4 + mat) * 64 * 72);
        uint4* dst = (uint4*)&Bs[mat][0][0];
        for (int idx = rg * 32 + lane; idx < 576; idx += 128)
            dst[idx] = src[idx];
    }
    if (rg == 0)
        for (int c = lane; c < 64; c += 32) bias_s[mat][c] = b[c] * scal;
    __syncthreads();

    int g = lane >> 2, tig = lane & 3;
    int r0 = rg * 16;

    unsigned afr[4][4];
    #pragma unroll
    for (int ks = 0; ks < 4; ks++) {
        int k0 = ks * 16;
        afr[ks][0] = *(const unsigned*)&As[r0 + g][k0 + 2 * tig];
        afr[ks][1] = *(const unsigned*)&As[r0 + g + 8][k0 + 2 * tig];
        afr[ks][2] = *(const unsigned*)&As[r0 + g][k0 + 2 * tig + 8];
        afr[ks][3] = *(const unsigned*)&As[r0 + g + 8][k0 + 2 * tig + 8];
    }

    int row0 = n0 + r0 + g;
    int row1 = row0 + 8;

    #pragma unroll
    for (int nt = 0; nt < 8; nt++) {
        int col = nt * 8 + 2 * tig;
        float c0 = bias_s[mat][col], c1 = bias_s[mat][col + 1];
        float c2 = c0, c3 = c1;
        #pragma unroll
        for (int ks = 0; ks < 4; ks++) {
            unsigned b0 = *(const unsigned*)&Bs[mat][nt * 8 + g][ks * 16 + 2 * tig];
            unsigned b1 = *(const unsigned*)&Bs[mat][nt * 8 + g][ks * 16 + 2 * tig + 8];
            asm volatile(
                "mma.sync.aligned.m16n8k16.row.col.f32.f16.f16.f32 "
                "{%0,%1,%2,%3}, {%4,%5,%6,%7}, {%8,%9}, {%0,%1,%2,%3};"
                : "+f"(c0), "+f"(c1), "+f"(c2), "+f"(c3)
                : "r"(afr[ks][0]), "r"(afr[ks][1]), "r"(afr[ks][2]), "r"(afr[ks][3]),
                  "r"(b0), "r"(b1));
        }
        if (mat == 0) {
            if (row0 < N_NODES) *(float2*)&g_q[row0 * 64 + col] = make_float2(c0, c1);
            if (row1 < N_NODES) *(float2*)&g_q[row1 * 64 + col] = make_float2(c2, c3);
        } else if (mat == 3) {
            if (row0 < N_NODES) *(float2*)&g_skip[row0 * 64 + col] = make_float2(c0, c1);
            if (row1 < N_NODES) *(float2*)&g_skip[row1 * 64 + col] = make_float2(c2, c3);
        } else {
            int off = (mat == 2) ? 64 : 0;
            if (row0 < N_NODES) *(__half2*)&g_kv[row0 * 128 + off + col] = __floats2half2_rn(c0, c1);
            if (row1 < N_NODES) *(__half2*)&g_kv[row1 * 128 + off + col] = __floats2half2_rn(c2, c3);
        }
    }
}

// ---------------- fused node kernel: warp/node, SW pipeline depth 4 ----------
#define LDKV(E) __ldg((const uint2*)g_kv + (((E) & 0xffffffffu) * 32 + lane))
#define NODE_BODY(E, R) { \
    float w_ = __uint_as_float((unsigned)((E) >> 32)); \
    float2 c01_ = __half22float2(*(const __half2*)&(R).x); \
    float2 c23_ = __half22float2(*(const __half2*)&(R).y); \
    float p_ = q4.x * c01_.x + q4.y * c01_.y + q4.z * c23_.x + q4.w * c23_.y; \
    p_ += __shfl_xor_sync(0xffffffffu, p_, 1, 4); \
    p_ += __shfl_xor_sync(0xffffffffu, p_, 2, 4); \
    float ph_ = __shfl_sync(0xffffffffu, p_, lane & 12, 32); \
    float ex_ = __expf(fmaf(w_, qwe, ph_)); \
    d += ex_; spw = fmaf(ex_, w_, spw); \
    acc.x = fmaf(ex_, c01_.x, acc.x); acc.y = fmaf(ex_, c01_.y, acc.y); \
    acc.z = fmaf(ex_, c23_.x, acc.z); acc.w = fmaf(ex_, c23_.y, acc.w); \
}

__global__ void k_node3(int li,
                        const float* __restrict__ Wedge,
                        const float* __restrict__ Wbeta,
                        const float* __restrict__ lng,
                        const float* __restrict__ lnb) {
    int n = blockIdx.x * (blockDim.x >> 5) + (threadIdx.x >> 5);
    if (n >= N_NODES) return;
    int lane = threadIdx.x & 31;
    int grp = lane & 15;

    float4 q4 = make_float4(0.f, 0.f, 0.f, 0.f);
    if (lane < 16) q4 = ((const float4*)g_q)[n * 16 + lane];
    float4 we = ((const float4*)Wedge)[li * 16 + grp];

    float pw = q4.x * we.x + q4.y * we.y + q4.z * we.z + q4.w * we.w;
    pw += __shfl_xor_sync(0xffffffffu, pw, 1, 4);
    pw += __shfl_xor_sync(0xffffffffu, pw, 2, 4);
    float qwe = __shfl_sync(0xffffffffu, pw, lane & 12, 32);

    int j0 = g_rowptr[n] + g_psum[n >> 10];
    int j1 = g_rowptr[n + 1] + g_psum[(n + 1) >> 10];
    int cnt = j1 - j0;
    const ull* ep = g_edge + j0;

    float d = 0.f, spw = 0.f;
    float4 acc = make_float4(0.f, 0.f, 0.f, 0.f);

    ull e0 = 0, e1 = 0, e2 = 0, e3 = 0;
    uint2 r0 = make_uint2(0u,0u), r1 = r0, r2 = r0, r3 = r0;
    if (cnt > 0) { e0 = __ldg(ep + 0); r0 = LDKV(e0); }
    if (cnt > 1) { e1 = __ldg(ep + 1); r1 = LDKV(e1); }
    if (cnt > 2) { e2 = __ldg(ep + 2); r2 = LDKV(e2); }
    if (cnt > 3) { e3 = __ldg(ep + 3); r3 = LDKV(e3); }

    int j = 0;
    for (; j + 8 <= cnt; j += 4) {
        NODE_BODY(e0, r0); e0 = __ldg(ep + j + 4); r0 = LDKV(e0);
        NODE_BODY(e1, r1); e1 = __ldg(ep + j + 5); r1 = LDKV(e1);
        NODE_BODY(e2, r2); e2 = __ldg(ep + j + 6); r2 = LDKV(e2);
        NODE_BODY(e3, r3); e3 = __ldg(ep + j + 7); r3 = LDKV(e3);
    }
    int left = cnt - j;
    if (left > 0) NODE_BODY(e0, r0);
    if (left > 1) NODE_BODY(e1, r1);
    if (left > 2) NODE_BODY(e2, r2);
    if (left > 3) NODE_BODY(e3, r3);
    for (int jj = j + 4; jj < cnt; jj++) {
        ull e = __ldg(ep + jj); uint2 r = LDKV(e);
        NODE_BODY(e, r);
    }

    if (lane >= 16) {
        float inv = 1.f / (d + 1e-16f);
        float4 o4;
        o4.x = (acc.x + we.x * spw) * inv;
        o4.y = (acc.y + we.y * spw) * inv;
        o4.z = (acc.z + we.z * spw) * inv;
        o4.w = (acc.w + we.w * spw) * inv;

        float4 xr = ((const float4*)g_skip)[n * 16 + grp];
        const float4* Wb = (const float4*)(Wbeta + li * 192);
        float4 w1 = Wb[grp], w2 = Wb[16 + grp], w3 = Wb[32 + grp];
        float contrib = o4.x * w1.x + o4.y * w1.y + o4.z * w1.z + o4.w * w1.w
                      + xr.x * w2.x + xr.y * w2.y + xr.z * w2.z + xr.w * w2.w
                      + (o4.x - xr.x) * w3.x + (o4.y - xr.y) * w3.y
                      + (o4.z - xr.z) * w3.z + (o4.w - xr.w) * w3.w;
        #pragma unroll
        for (int o = 8; o >= 1; o >>= 1)
            contrib += __shfl_xor_sync(0xffff0000u, contrib, o);
        float beta = 1.f / (1.f + __expf(-contrib));

        float4 hres = ((const float4*)g_h)[n * 16 + grp];
        float4 z;
        z.x = fmaf(beta, xr.x - o4.x, o4.x) + hres.x;
        z.y = fmaf(beta, xr.y - o4.y, o4.y) + hres.y;
        z.z = fmaf(beta, xr.z - o4.z, o4.z) + hres.z;
        z.w = fmaf(beta, xr.w - o4.w, o4.w) + hres.w;

        float s1 = z.x + z.y + z.z + z.w;
        float s2 = z.x * z.x + z.y * z.y + z.z * z.z + z.w * z.w;
        #pragma unroll
        for (int o = 8; o >= 1; o >>= 1) {
            s1 += __shfl_xor_sync(0xffff0000u, s1, o);
            s2 += __shfl_xor_sync(0xffff0000u, s2, o);
        }
        float mu  = s1 * (1.f / 64.f);
        float var = s2 * (1.f / 64.f) - mu * mu;
        float rstd = rsqrtf(var + LN_EPS);
        float4 g = ((const float4*)lng)[li * 16 + grp];
        float4 b = ((const float4*)lnb)[li * 16 + grp];
        float4 hout;
        hout.x = (z.x - mu) * rstd * g.x + b.x;
        hout.y = (z.y - mu) * rstd * g.y + b.y;
        hout.z = (z.z - mu) * rstd * g.z + b.z;
        hout.w = (z.w - mu) * rstd * g.w + b.w;
        ((float4*)g_h)[n * 16 + grp] = hout;
    }
}

// ---------------- head -------------------------------------------------------
__global__ void k_final(const float* __restrict__ Wc1, const float* __restrict__ bc1,
                        const float* __restrict__ Wc2, const float* __restrict__ bc2,
                        float* __restrict__ out) {
    __shared__ __align__(16) float hs[64 * 64];
    __shared__ __align__(16) float h1s[64 * 64];
    int t = threadIdx.x;
    int n0 = blockIdx.x * 64;
    float4* hs4 = (float4*)hs;
    for (int idx = t; idx < 1024; idx += 256) {
        int row = n0 + (idx >> 4);
        hs4[idx] = (row < N_NODES) ? ((const float4*)g_h)[row * 16 + (idx & 15)]
                                   : make_float4(0.f, 0.f, 0.f, 0.f);
    }
    int c = t & 63, rg = t >> 6;
    ull w2[32];
    #pragma unroll
    for (int k = 0; k < 32; k++)
        w2[k] = packf2(Wc1[(2 * k) * 64 + c], Wc1[(2 * k + 1) * 64 + c]);
    float b1 = bc1[c];
    __syncthreads();
    for (int r = rg * 16; r < rg * 16 + 16; r++) {
        const ulonglong2* hr = (const ulonglong2*)&hs[r * 64];
        ull acc_a = packf2(b1, 0.f), acc_b = 0ull;
        #pragma unroll
        for (int kk = 0; kk < 16; kk++) {
            ulonglong2 hv = hr[kk];
            acc_a = ff2(w2[2 * kk + 0], hv.x, acc_a);
            acc_b = ff2(w2[2 * kk + 1], hv.y, acc_b);
        }
        h1s[r * 64 + c] = fmaxf(sum2(acc_a) + sum2(acc_b), 0.f);
    }
    __syncthreads();
    if (t < 240) {
        int c2 = t % 12, rg2 = t / 12;
        ull wr2[32];
        #pragma unroll
        for (int k = 0; k < 32; k++)
            wr2[k] = packf2(Wc2[(2 * k) * NC + c2], Wc2[(2 * k + 1) * NC + c2]);
        float b2 = bc2[c2];
        int rmax = min(64, N_NODES - n0);
        for (int r = rg2; r < rmax; r += 20) {
            const ulonglong2* hr = (const ulonglong2*)&h1s[r * 64];
            ull acc_a = packf2(b2, 0.f), acc_b = 0ull;
            #pragma unroll
            for (int kk = 0; kk < 16; kk++) {
                ulonglong2 hv = hr[kk];
                acc_a = ff2(wr2[2 * kk + 0], hv.x, acc_a);
                acc_b = ff2(wr2[2 * kk + 1], hv.y, acc_b);
            }
            out[(n0 + r) * NC + c2] = sum2(acc_a) + sum2(acc_b);
        }
    }
}

// ---------------- launch -----------------------------------------------------
extern "C" void kernel_launch(void* const* d_in, const int* in_sizes, int n_in,
                              void* d_out, int out_size) {
    const float* x     = (const float*)d_in[0];
    const int*   ei    = (const int*)  d_in[1];
    const float* ea    = (const float*)d_in[2];
    const float* Win   = (const float*)d_in[3];
    const float* b_in  = (const float*)d_in[4];
    const float* Wq    = (const float*)d_in[5];
    const float* bq    = (const float*)d_in[6];
    const float* Wk    = (const float*)d_in[7];
    const float* bk    = (const float*)d_in[8];
    const float* Wv    = (const float*)d_in[9];
    const float* bv    = (const float*)d_in[10];
    const float* Wedge = (const float*)d_in[11];
    const float* Wskip = (const float*)d_in[12];
    const float* bskip = (const float*)d_in[13];
    const float* Wbeta = (const float*)d_in[14];
    const float* ln_g  = (const float*)d_in[15];
    const float* ln_b  = (const float*)d_in[16];
    const float* Wc1   = (const float*)d_in[17];
    const float* bc1   = (const float*)d_in[18];
    const float* Wc2   = (const float*)d_in[19];
    const float* bc2   = (const float*)d_in[20];
    float* out = (float*)d_out;

    int nrb = (N_NODES + 63) / 64;

    // launch #4 = k_gemm4 (ncu capture slot)
    k_ingemm<<<nrb, 256>>>(x, Win, b_in);                               // 1
    k_prep_w<<<(12 * 4096 + 255) / 256, 256>>>(Wq, Wk, Wv, Wskip);      // 2
    k_hist<<<(N_EDGES + 255) / 256, 256>>>(ei);                         // 3
    k_gemm4<<<nrb, 512>>>(0, bq, bk, bv, bskip);                        // 4 (profiled)
    k_scan1<<<SCAN_BLK, 1024>>>();                                      // 5
    k_scan2<<<1, 64>>>();                                               // 6
    k_scatter<<<(N_EDGES + 255) / 256, 256>>>(ei, ea);                  // 7
    k_node3<<<(N_NODES + 7) / 8, 256>>>(0, Wedge, Wbeta, ln_g, ln_b);   // 8

    for (int li = 1; li < NLAYERS; li++) {
        k_gemm4<<<nrb, 512>>>(li, bq, bk, bv, bskip);
        k_node3<<<(N_NODES + 7) / 8, 256>>>(li, Wedge, Wbeta, ln_g, ln_b);
    }

    k_final<<<nrb, 256>>>(Wc1, bc1, Wc2, bc2, out);
}

// round 9
// speedup vs baseline: 1.4103x; 1.0670x over previous
#include <cuda_runtime.h>
#include <cuda_fp16.h>
#include <math.h>

#define N_NODES 50000
#define N_EDGES 800000
#define IN_DIM 50
#define HID 64
#define HEADS 4
#define NLAYERS 3
#define NC 12
#define INV_SQRT_C 0.25f
#define LN_EPS 1e-5f
#define SCAN_BLK ((N_NODES + 1023) / 1024)   // 49
#define NTILES ((N_NODES + 63) / 64)         // 782

typedef unsigned long long ull;

__device__ __forceinline__ ull ff2(ull a, ull b, ull c) {
    ull d;
    asm("fma.rn.f32x2 %0, %1, %2, %3;" : "=l"(d) : "l"(a), "l"(b), "l"(c));
    return d;
}
__device__ __forceinline__ ull packf2(float lo, float hi) {
    return ((ull)__float_as_uint(hi) << 32) | (ull)__float_as_uint(lo);
}
__device__ __forceinline__ float sum2(ull v) {
    return __uint_as_float((unsigned)(v & 0xffffffffu)) + __uint_as_float((unsigned)(v >> 32));
}

// ---------------- scratch ----------------------------------------------------
__device__ __align__(16) float  g_h[N_NODES * HID];
__device__ __align__(16) __half g_hh[N_NODES * HID];    // fp16 mirror of h
__device__ __align__(16) float  g_q[N_NODES * HID];
__device__ __align__(16) float  g_skip[N_NODES * HID];
__device__ __align__(16) __half g_kv[N_NODES * 128];
__device__ __align__(16) __half g_wt[13 * 64 * 72];     // 12 layer mats + Wc1, fp16 W^T
__device__ int   g_cnt[N_NODES];
__device__ int   g_rowptr[N_NODES + 1];
__device__ int   g_fill[N_NODES];
__device__ ull   g_edge[N_EDGES];
__device__ int   g_psum[64];

// ---------------- weight precompute ------------------------------------------
__global__ void k_prep_w(const float* __restrict__ Wq, const float* __restrict__ Wk,
                         const float* __restrict__ Wv, const float* __restrict__ Wsk,
                         const float* __restrict__ Wc1) {
    int id = blockIdx.x * blockDim.x + threadIdx.x;   // 13*4096
    if (id >= 13 * 4096) return;
    int k = id & 63, n = (id >> 6) & 63, m = id >> 12;
    const float* W;
    float scal = 1.f;
    if (m == 12) W = Wc1;
    else {
        int li = m >> 2, mat = m & 3;
        if (mat == 0)      { W = Wq + li * 4096; scal = INV_SQRT_C; }
        else if (mat == 1) W = Wk  + li * 4096;
        else if (mat == 2) W = Wv  + li * 4096;
        else               W = Wsk + li * 4096;
    }
    g_wt[(m * 64 + n) * 72 + k] = __float2half_rn(W[k * 64 + n] * scal);
}

// ---------------- CSR build --------------------------------------------------
__global__ void k_hist(const int* __restrict__ ei) {
    int e = blockIdx.x * blockDim.x + threadIdx.x;
    if (e < N_NODES) g_fill[e] = 0;
    if (e < N_EDGES) atomicAdd(&g_cnt[ei[N_EDGES + e]], 1);
}

__global__ void k_scan1() {
    __shared__ int wsum[32];
    int t = threadIdx.x, lane = t & 31, wid = t >> 5;
    int i = blockIdx.x * 1024 + t;
    int v = (i < N_NODES) ? g_cnt[i] : 0;
    if (i < N_NODES) g_cnt[i] = 0;
    int incl = v;
    #pragma unroll
    for (int o = 1; o < 32; o <<= 1) {
        int u = __shfl_up_sync(0xffffffffu, incl, o);
        if (lane >= o) incl += u;
    }
    if (lane == 31) wsum[wid] = incl;
    __syncthreads();
    if (wid == 0) {
        int ws = wsum[lane];
        int wincl = ws;
        #pragma unroll
        for (int o = 1; o < 32; o <<= 1) {
            int u = __shfl_up_sync(0xffffffffu, wincl, o);
            if (lane >= o) wincl += u;
        }
        wsum[lane] = wincl - ws;
        if (lane == 31) g_psum[blockIdx.x] = wincl;
    }
    __syncthreads();
    int excl = incl - v + wsum[wid];
    if (i < N_NODES) g_rowptr[i] = excl;
}

__global__ void k_scan2() {
    __shared__ int w0tot;
    int t = threadIdx.x, lane = t & 31;
    int v = (t < SCAN_BLK) ? g_psum[t] : 0;
    int incl = v;
    #pragma unroll
    for (int o = 1; o < 32; o <<= 1) {
        int u = __shfl_up_sync(0xffffffffu, incl, o);
        if (lane >= o) incl += u;
    }
    if (t == 31) w0tot = incl;
    __syncthreads();
    int excl = incl - v + ((t >= 32) ? w0tot : 0);
    if (t < SCAN_BLK) g_psum[t] = excl;
    if (t == SCAN_BLK - 1) g_rowptr[N_NODES] = v;
}

__global__ void k_scatter(const int* __restrict__ ei, const float* __restrict__ ea) {
    int e = blockIdx.x * blockDim.x + threadIdx.x;
    if (e < N_EDGES) {
        int dst = ei[N_EDGES + e];
        int base = g_rowptr[dst] + g_psum[dst >> 10];
        int pos = base + atomicAdd(&g_fill[dst], 1);
        g_edge[pos] = ((ull)__float_as_uint(ea[e]) << 32) | (unsigned)ei[e];
    }
}

// ---------------- input GEMM -------------------------------------------------
__global__ void k_ingemm(const float* __restrict__ x,
                         const float* __restrict__ Win,
                         const float* __restrict__ b_in) {
    __shared__ __align__(16) float xs[64 * 52];
    int t = threadIdx.x;
    int c = t & 63, rg = t >> 6;
    ull w2[26];
    #pragma unroll
    for (int k = 0; k < 25; k++)
        w2[k] = packf2(Win[(2 * k) * HID + c], Win[(2 * k + 1) * HID + c]);
    w2[25] = 0ull;
    int n0 = blockIdx.x * 64;
    for (int idx = t; idx < 64 * IN_DIM; idx += 256) {
        int r = idx / IN_DIM, k = idx % IN_DIM;
        int row = n0 + r;
        xs[r * 52 + k] = (row < N_NODES) ? x[row * IN_DIM + k] : 0.f;
    }
    if (rg == 0) { xs[c * 52 + 50] = 0.f; xs[c * 52 + 51] = 0.f; }
    __syncthreads();
    float bias = b_in[c];
    int rend = min(rg * 16 + 16, N_NODES - n0);
    for (int r = rg * 16; r < rend; r++) {
        const ulonglong2* hr = (const ulonglong2*)&xs[r * 52];
        ull acc_a = packf2(bias, 0.f), acc_b = 0ull;
        #pragma unroll
        for (int kk = 0; kk < 13; kk++) {
            ulonglong2 hv = hr[kk];
            acc_a = ff2(w2[2 * kk + 0], hv.x, acc_a);
            acc_b = ff2(w2[2 * kk + 1], hv.y, acc_b);
        }
        float acc = sum2(acc_a) + sum2(acc_b);
        g_h[(n0 + r) * HID + c] = acc;
        g_hh[(n0 + r) * HID + c] = __float2half_rn(acc);
    }
}

// ---------------- q/k/v/skip GEMM: HMMA, persistent 2 tiles/block ------------
__global__ __launch_bounds__(512) void k_gemm4(int li,
                        const float* __restrict__ bq, const float* __restrict__ bk,
                        const float* __restrict__ bv, const float* __restrict__ bsk) {
    __shared__ __half As[64][72];
    __shared__ __half Bs[4][64][72];
    __shared__ float  bias_s[4][64];

    int t = threadIdx.x;
    int w = t >> 5, lane = t & 31;
    int mat = w & 3, rg = w >> 2;

    const float* b;
    if (mat == 0)      b = bq  + li * 64;
    else if (mat == 1) b = bk  + li * 64;
    else if (mat == 2) b = bv  + li * 64;
    else               b = bsk + li * 64;
    float scal = (mat == 0) ? INV_SQRT_C : 1.f;

    // one-time: weights + bias
    {
        const uint4* src = (const uint4*)(g_wt + (li * 4 + mat) * 64 * 72);
        uint4* dst = (uint4*)&Bs[mat][0][0];
        for (int idx = rg * 32 + lane; idx < 576; idx += 128)
            dst[idx] = src[idx];
        if (rg == 0)
            for (int c = lane; c < 64; c += 32) bias_s[mat][c] = b[c] * scal;
    }

    int g = lane >> 2, tig = lane & 3;
    int r0 = rg * 16;
    int arow = t >> 3, acol = (t & 7) * 8;   // staging coords: 8 halves per thread

    for (int tile = blockIdx.x; tile < NTILES; tile += gridDim.x) {
        int n0 = tile * 64;
        __syncthreads();    // previous tile's reads done before overwrite
        // stage A: one uint4 per thread from fp16 mirror
        {
            int row = n0 + arow;
            uint4 v = make_uint4(0u, 0u, 0u, 0u);
            if (row < N_NODES) v = *(const uint4*)&g_hh[row * 64 + acol];
            *(uint4*)&As[arow][acol] = v;
        }
        __syncthreads();

        unsigned afr[4][4];
        #pragma unroll
        for (int ks = 0; ks < 4; ks++) {
            int k0 = ks * 16;
            afr[ks][0] = *(const unsigned*)&As[r0 + g][k0 + 2 * tig];
            afr[ks][1] = *(const unsigned*)&As[r0 + g + 8][k0 + 2 * tig];
            afr[ks][2] = *(const unsigned*)&As[r0 + g][k0 + 2 * tig + 8];
            afr[ks][3] = *(const unsigned*)&As[r0 + g + 8][k0 + 2 * tig + 8];
        }

        int row0 = n0 + r0 + g;
        int row1 = row0 + 8;

        #pragma unroll
        for (int nt = 0; nt < 8; nt++) {
            int col = nt * 8 + 2 * tig;
            float c0 = bias_s[mat][col], c1 = bias_s[mat][col + 1];
            float c2 = c0, c3 = c1;
            #pragma unroll
            for (int ks = 0; ks < 4; ks++) {
                unsigned b0 = *(const unsigned*)&Bs[mat][nt * 8 + g][ks * 16 + 2 * tig];
                unsigned b1 = *(const unsigned*)&Bs[mat][nt * 8 + g][ks * 16 + 2 * tig + 8];
                asm volatile(
                    "mma.sync.aligned.m16n8k16.row.col.f32.f16.f16.f32 "
                    "{%0,%1,%2,%3}, {%4,%5,%6,%7}, {%8,%9}, {%0,%1,%2,%3};"
                    : "+f"(c0), "+f"(c1), "+f"(c2), "+f"(c3)
                    : "r"(afr[ks][0]), "r"(afr[ks][1]), "r"(afr[ks][2]), "r"(afr[ks][3]),
                      "r"(b0), "r"(b1));
            }
            if (mat == 0) {
                if (row0 < N_NODES) *(float2*)&g_q[row0 * 64 + col] = make_float2(c0, c1);
                if (row1 < N_NODES) *(float2*)&g_q[row1 * 64 + col] = make_float2(c2, c3);
            } else if (mat == 3) {
                if (row0 < N_NODES) *(float2*)&g_skip[row0 * 64 + col] = make_float2(c0, c1);
                if (row1 < N_NODES) *(float2*)&g_skip[row1 * 64 + col] = make_float2(c2, c3);
            } else {
                int off = (mat == 2) ? 64 : 0;
                if (row0 < N_NODES) *(__half2*)&g_kv[row0 * 128 + off + col] = __floats2half2_rn(c0, c1);
                if (row1 < N_NODES) *(__half2*)&g_kv[row1 * 128 + off + col] = __floats2half2_rn(c2, c3);
            }
        }
    }
}

// ---------------- fused node kernel ------------------------------------------
#define LDKV(E) __ldg((const uint2*)g_kv + (((E) & 0xffffffffu) * 32 + lane))
#define NODE_BODY(E, R) { \
    float w_ = __uint_as_float((unsigned)((E) >> 32)); \
    float2 c01_ = __half22float2(*(const __half2*)&(R).x); \
    float2 c23_ = __half22float2(*(const __half2*)&(R).y); \
    float p_ = q4.x * c01_.x + q4.y * c01_.y + q4.z * c23_.x + q4.w * c23_.y; \
    p_ += __shfl_xor_sync(0xffffffffu, p_, 1, 4); \
    p_ += __shfl_xor_sync(0xffffffffu, p_, 2, 4); \
    float ph_ = __shfl_sync(0xffffffffu, p_, lane & 12, 32); \
    float ex_ = __expf(fmaf(w_, qwe, ph_)); \
    d += ex_; spw = fmaf(ex_, w_, spw); \
    acc.x = fmaf(ex_, c01_.x, acc.x); acc.y = fmaf(ex_, c01_.y, acc.y); \
    acc.z = fmaf(ex_, c23_.x, acc.z); acc.w = fmaf(ex_, c23_.y, acc.w); \
}

__global__ void k_node3(int li,
                        const float* __restrict__ Wedge,
                        const float* __restrict__ Wbeta,
                        const float* __restrict__ lng,
                        const float* __restrict__ lnb) {
    int n = blockIdx.x * (blockDim.x >> 5) + (threadIdx.x >> 5);
    if (n >= N_NODES) return;
    int lane = threadIdx.x & 31;
    int grp = lane & 15;

    float4 q4 = make_float4(0.f, 0.f, 0.f, 0.f);
    if (lane < 16) q4 = ((const float4*)g_q)[n * 16 + lane];
    float4 we = ((const float4*)Wedge)[li * 16 + grp];

    float pw = q4.x * we.x + q4.y * we.y + q4.z * we.z + q4.w * we.w;
    pw += __shfl_xor_sync(0xffffffffu, pw, 1, 4);
    pw += __shfl_xor_sync(0xffffffffu, pw, 2, 4);
    float qwe = __shfl_sync(0xffffffffu, pw, lane & 12, 32);

    int j0 = g_rowptr[n] + g_psum[n >> 10];
    int j1 = g_rowptr[n + 1] + g_psum[(n + 1) >> 10];
    int cnt = j1 - j0;
    const ull* ep = g_edge + j0;

    float d = 0.f, spw = 0.f;
    float4 acc = make_float4(0.f, 0.f, 0.f, 0.f);

    ull e0 = 0, e1 = 0, e2 = 0, e3 = 0;
    uint2 r0 = make_uint2(0u,0u), r1 = r0, r2 = r0, r3 = r0;
    if (cnt > 0) { e0 = __ldg(ep + 0); r0 = LDKV(e0); }
    if (cnt > 1) { e1 = __ldg(ep + 1); r1 = LDKV(e1); }
    if (cnt > 2) { e2 = __ldg(ep + 2); r2 = LDKV(e2); }
    if (cnt > 3) { e3 = __ldg(ep + 3); r3 = LDKV(e3); }

    int j = 0;
    for (; j + 8 <= cnt; j += 4) {
        NODE_BODY(e0, r0); e0 = __ldg(ep + j + 4); r0 = LDKV(e0);
        NODE_BODY(e1, r1); e1 = __ldg(ep + j + 5); r1 = LDKV(e1);
        NODE_BODY(e2, r2); e2 = __ldg(ep + j + 6); r2 = LDKV(e2);
        NODE_BODY(e3, r3); e3 = __ldg(ep + j + 7); r3 = LDKV(e3);
    }
    int left = cnt - j;
    if (left > 0) NODE_BODY(e0, r0);
    if (left > 1) NODE_BODY(e1, r1);
    if (left > 2) NODE_BODY(e2, r2);
    if (left > 3) NODE_BODY(e3, r3);
    for (int jj = j + 4; jj < cnt; jj++) {
        ull e = __ldg(ep + jj); uint2 r = LDKV(e);
        NODE_BODY(e, r);
    }

    if (lane >= 16) {
        float inv = 1.f / (d + 1e-16f);
        float4 o4;
        o4.x = (acc.x + we.x * spw) * inv;
        o4.y = (acc.y + we.y * spw) * inv;
        o4.z = (acc.z + we.z * spw) * inv;
        o4.w = (acc.w + we.w * spw) * inv;

        float4 xr = ((const float4*)g_skip)[n * 16 + grp];
        const float4* Wb = (const float4*)(Wbeta + li * 192);
        float4 w1 = Wb[grp], w2 = Wb[16 + grp], w3 = Wb[32 + grp];
        float contrib = o4.x * w1.x + o4.y * w1.y + o4.z * w1.z + o4.w * w1.w
                      + xr.x * w2.x + xr.y * w2.y + xr.z * w2.z + xr.w * w2.w
                      + (o4.x - xr.x) * w3.x + (o4.y - xr.y) * w3.y
                      + (o4.z - xr.z) * w3.z + (o4.w - xr.w) * w3.w;
        #pragma unroll
        for (int o = 8; o >= 1; o >>= 1)
            contrib += __shfl_xor_sync(0xffff0000u, contrib, o);
        float beta = 1.f / (1.f + __expf(-contrib));

        float4 hres = ((const float4*)g_h)[n * 16 + grp];
        float4 z;
        z.x = fmaf(beta, xr.x - o4.x, o4.x) + hres.x;
        z.y = fmaf(beta, xr.y - o4.y, o4.y) + hres.y;
        z.z = fmaf(beta, xr.z - o4.z, o4.z) + hres.z;
        z.w = fmaf(beta, xr.w - o4.w, o4.w) + hres.w;

        float s1 = z.x + z.y + z.z + z.w;
        float s2 = z.x * z.x + z.y * z.y + z.z * z.z + z.w * z.w;
        #pragma unroll
        for (int o = 8; o >= 1; o >>= 1) {
            s1 += __shfl_xor_sync(0xffff0000u, s1, o);
            s2 += __shfl_xor_sync(0xffff0000u, s2, o);
        }
        float mu  = s1 * (1.f / 64.f);
        float var = s2 * (1.f / 64.f) - mu * mu;
        float rstd = rsqrtf(var + LN_EPS);
        float4 g = ((const float4*)lng)[li * 16 + grp];
        float4 b = ((const float4*)lnb)[li * 16 + grp];
        float4 hout;
        hout.x = (z.x - mu) * rstd * g.x + b.x;
        hout.y = (z.y - mu) * rstd * g.y + b.y;
        hout.z = (z.z - mu) * rstd * g.z + b.z;
        hout.w = (z.w - mu) * rstd * g.w + b.w;
        ((float4*)g_h)[n * 16 + grp] = hout;
        // fp16 mirror (8B per lane, coalesced)
        __half2 hh01 = __floats2half2_rn(hout.x, hout.y);
        __half2 hh23 = __floats2half2_rn(hout.z, hout.w);
        uint2 pk; pk.x = *(unsigned*)&hh01; pk.y = *(unsigned*)&hh23;
        ((uint2*)g_hh)[n * 16 + grp] = pk;
    }
}

// ---------------- head: stage1 HMMA + stage2 FFMA2 ---------------------------
__global__ __launch_bounds__(256) void k_final(const float* __restrict__ bc1,
                        const float* __restrict__ Wc2, const float* __restrict__ bc2,
                        float* __restrict__ out) {
    __shared__ __half As[64][72];
    __shared__ __half Bs[64][72];
    __shared__ __align__(16) float h1s[64 * 64];
    __shared__ float bias1[64];

    int t = threadIdx.x;
    int w = t >> 5, lane = t & 31;
    int n0 = blockIdx.x * 64;

    // stage A (fp16 mirror) : 2 uint4 per thread
    for (int idx = t; idx < 512; idx += 256) {
        int row = n0 + (idx >> 3), col = (idx & 7) * 8;
        uint4 v = make_uint4(0u, 0u, 0u, 0u);
        if (row < N_NODES) v = *(const uint4*)&g_hh[row * 64 + col];
        *(uint4*)&As[idx >> 3][col] = v;
    }
    // stage Wc1^T (precomputed, matrix 12)
    {
        const uint4* src = (const uint4*)(g_wt + 12 * 64 * 72);
        uint4* dst = (uint4*)&Bs[0][0];
        for (int idx = t; idx < 576; idx += 256) dst[idx] = src[idx];
    }
    if (t < 64) bias1[t] = bc1[t];
    __syncthreads();

    // stage1: 8 warps = 4 rowgroups x 2 col-halves
    {
        int rg = w & 3, nh = w >> 2;
        int g = lane >> 2, tig = lane & 3;
        int r0 = rg * 16;
        unsigned afr[4][4];
        #pragma unroll
        for (int ks = 0; ks < 4; ks++) {
            int k0 = ks * 16;
            afr[ks][0] = *(const unsigned*)&As[r0 + g][k0 + 2 * tig];
            afr[ks][1] = *(const unsigned*)&As[r0 + g + 8][k0 + 2 * tig];
            afr[ks][2] = *(const unsigned*)&As[r0 + g][k0 + 2 * tig + 8];
            afr[ks][3] = *(const unsigned*)&As[r0 + g + 8][k0 + 2 * tig + 8];
        }
        #pragma unroll
        for (int q = 0; q < 4; q++) {
            int nt = nh * 4 + q;
            int col = nt * 8 + 2 * tig;
            float c0 = bias1[col], c1 = bias1[col + 1];
            float c2 = c0, c3 = c1;
            #pragma unroll
            for (int ks = 0; ks < 4; ks++) {
                unsigned b0 = *(const unsigned*)&Bs[nt * 8 + g][ks * 16 + 2 * tig];
                unsigned b1 = *(const unsigned*)&Bs[nt * 8 + g][ks * 16 + 2 * tig + 8];
                asm volatile(
                    "mma.sync.aligned.m16n8k16.row.col.f32.f16.f16.f32 "
                    "{%0,%1,%2,%3}, {%4,%5,%6,%7}, {%8,%9}, {%0,%1,%2,%3};"
                    : "+f"(c0), "+f"(c1), "+f"(c2), "+f"(c3)
                    : "r"(afr[ks][0]), "r"(afr[ks][1]), "r"(afr[ks][2]), "r"(afr[ks][3]),
                      "r"(b0), "r"(b1));
            }
            *(float2*)&h1s[(r0 + g) * 64 + col]     = make_float2(fmaxf(c0, 0.f), fmaxf(c1, 0.f));
            *(float2*)&h1s[(r0 + g + 8) * 64 + col] = make_float2(fmaxf(c2, 0.f), fmaxf(c3, 0.f));
        }
    }
    __syncthreads();

    // stage2: 240 threads, NC=12 cols
    if (t < 240) {
        int c2 = t % 12, rg2 = t / 12;
        ull wr2[32];
        #pragma unroll
        for (int k = 0; k < 32; k++)
            wr2[k] = packf2(Wc2[(2 * k) * NC + c2], Wc2[(2 * k + 1) * NC + c2]);
        float b2 = bc2[c2];
        int rmax = min(64, N_NODES - n0);
        for (int r = rg2; r < rmax; r += 20) {
            const ulonglong2* hr = (const ulonglong2*)&h1s[r * 64];
            ull acc_a = packf2(b2, 0.f), acc_b = 0ull;
            #pragma unroll
            for (int kk = 0; kk < 16; kk++) {
                ulonglong2 hv = hr[kk];
                acc_a = ff2(wr2[2 * kk + 0], hv.x, acc_a);
                acc_b = ff2(wr2[2 * kk + 1], hv.y, acc_b);
            }
            out[(n0 + r) * NC + c2] = sum2(acc_a) + sum2(acc_b);
        }
    }
}

// ---------------- launch -----------------------------------------------------
extern "C" void kernel_launch(void* const* d_in, const int* in_sizes, int n_in,
                              void* d_out, int out_size) {
    const float* x     = (const float*)d_in[0];
    const int*   ei    = (const int*)  d_in[1];
    const float* ea    = (const float*)d_in[2];
    const float* Win   = (const float*)d_in[3];
    const float* b_in  = (const float*)d_in[4];
    const float* Wq    = (const float*)d_in[5];
    const float* bq    = (const float*)d_in[6];
    const float* Wk    = (const float*)d_in[7];
    const float* bk    = (const float*)d_in[8];
    const float* Wv    = (const float*)d_in[9];
    const float* bv    = (const float*)d_in[10];
    const float* Wedge = (const float*)d_in[11];
    const float* Wskip = (const float*)d_in[12];
    const float* bskip = (const float*)d_in[13];
    const float* Wbeta = (const float*)d_in[14];
    const float* ln_g  = (const float*)d_in[15];
    const float* ln_b  = (const float*)d_in[16];
    const float* Wc1   = (const float*)d_in[17];
    const float* bc1   = (const float*)d_in[18];
    const float* Wc2   = (const float*)d_in[19];
    const float* bc2   = (const float*)d_in[20];
    float* out = (float*)d_out;

    int nrb = NTILES;

    // launch #4 = k_gemm4 (ncu capture slot)
    k_ingemm<<<nrb, 256>>>(x, Win, b_in);                               // 1
    k_prep_w<<<(13 * 4096 + 255) / 256, 256>>>(Wq, Wk, Wv, Wskip, Wc1); // 2
    k_hist<<<(N_EDGES + 255) / 256, 256>>>(ei);                         // 3
    k_gemm4<<<(NTILES + 1) / 2, 512>>>(0, bq, bk, bv, bskip);           // 4 (profiled)
    k_scan1<<<SCAN_BLK, 1024>>>();                                      // 5
    k_scan2<<<1, 64>>>();                                               // 6
    k_scatter<<<(N_EDGES + 255) / 256, 256>>>(ei, ea);                  // 7
    k_node3<<<(N_NODES + 7) / 8, 256>>>(0, Wedge, Wbeta, ln_g, ln_b);   // 8

    for (int li = 1; li < NLAYERS; li++) {
        k_gemm4<<<(NTILES + 1) / 2, 512>>>(li, bq, bk, bv, bskip);
        k_node3<<<(N_NODES + 7) / 8, 256>>>(li, Wedge, Wbeta, ln_g, ln_b);
    }

    k_final<<<nrb, 256>>>(bc1, Wc2, bc2, out);
}

// round 10
// speedup vs baseline: 1.5737x; 1.1159x over previous
#include <cuda_runtime.h>
#include <cuda_fp16.h>
#include <math.h>

#define N_NODES 50000
#define N_EDGES 800000
#define IN_DIM 50
#define HID 64
#define HEADS 4
#define NLAYERS 3
#define NC 12
#define INV_SQRT_C 0.25f
#define LN_EPS 1e-5f
#define SCAN_BLK ((N_NODES + 1023) / 1024)   // 49
#define NTILES ((N_NODES + 63) / 64)         // 782

typedef unsigned long long ull;

__device__ __forceinline__ ull ff2(ull a, ull b, ull c) {
    ull d;
    asm("fma.rn.f32x2 %0, %1, %2, %3;" : "=l"(d) : "l"(a), "l"(b), "l"(c));
    return d;
}
__device__ __forceinline__ ull packf2(float lo, float hi) {
    return ((ull)__float_as_uint(hi) << 32) | (ull)__float_as_uint(lo);
}
__device__ __forceinline__ float sum2(ull v) {
    return __uint_as_float((unsigned)(v & 0xffffffffu)) + __uint_as_float((unsigned)(v >> 32));
}

// ---------------- scratch ----------------------------------------------------
__device__ __align__(16) float  g_h[N_NODES * HID];
__device__ __align__(16) __half g_hh[N_NODES * HID];    // fp16 mirror of h
__device__ __align__(16) float  g_q[N_NODES * HID];
__device__ __align__(16) float  g_skip[N_NODES * HID];
// interleaved kv: per node, lane L (0..31) owns halves {k[2L],k[2L+1],v[2L],v[2L+1]}
__device__ __align__(16) __half g_kv[N_NODES * 128];
__device__ __align__(16) __half g_wt[13 * 64 * 72];     // 12 layer mats + Wc1, fp16 W^T
__device__ int   g_cnt[N_NODES];
__device__ int   g_rowptr[N_NODES + 1];
__device__ int   g_fill[N_NODES];
__device__ ull   g_edge[N_EDGES];
__device__ int   g_psum[64];

// ---------------- weight precompute ------------------------------------------
__global__ void k_prep_w(const float* __restrict__ Wq, const float* __restrict__ Wk,
                         const float* __restrict__ Wv, const float* __restrict__ Wsk,
                         const float* __restrict__ Wc1) {
    int id = blockIdx.x * blockDim.x + threadIdx.x;   // 13*4096
    if (id >= 13 * 4096) return;
    int k = id & 63, n = (id >> 6) & 63, m = id >> 12;
    const float* W;
    float scal = 1.f;
    if (m == 12) W = Wc1;
    else {
        int li = m >> 2, mat = m & 3;
        if (mat == 0)      { W = Wq + li * 4096; scal = INV_SQRT_C; }
        else if (mat == 1) W = Wk  + li * 4096;
        else if (mat == 2) W = Wv  + li * 4096;
        else               W = Wsk + li * 4096;
    }
    g_wt[(m * 64 + n) * 72 + k] = __float2half_rn(W[k * 64 + n] * scal);
}

// ---------------- CSR build --------------------------------------------------
__global__ void k_hist(const int* __restrict__ ei) {
    int e = blockIdx.x * blockDim.x + threadIdx.x;
    if (e < N_NODES) g_fill[e] = 0;
    if (e < N_EDGES) atomicAdd(&g_cnt[ei[N_EDGES + e]], 1);
}

__global__ void k_scan1() {
    __shared__ int wsum[32];
    int t = threadIdx.x, lane = t & 31, wid = t >> 5;
    int i = blockIdx.x * 1024 + t;
    int v = (i < N_NODES) ? g_cnt[i] : 0;
    if (i < N_NODES) g_cnt[i] = 0;
    int incl = v;
    #pragma unroll
    for (int o = 1; o < 32; o <<= 1) {
        int u = __shfl_up_sync(0xffffffffu, incl, o);
        if (lane >= o) incl += u;
    }
    if (lane == 31) wsum[wid] = incl;
    __syncthreads();
    if (wid == 0) {
        int ws = wsum[lane];
        int wincl = ws;
        #pragma unroll
        for (int o = 1; o < 32; o <<= 1) {
            int u = __shfl_up_sync(0xffffffffu, wincl, o);
            if (lane >= o) wincl += u;
        }
        wsum[lane] = wincl - ws;
        if (lane == 31) g_psum[blockIdx.x] = wincl;
    }
    __syncthreads();
    int excl = incl - v + wsum[wid];
    if (i < N_NODES) g_rowptr[i] = excl;
}

__global__ void k_scan2() {
    __shared__ int w0tot;
    int t = threadIdx.x, lane = t & 31;
    int v = (t < SCAN_BLK) ? g_psum[t] : 0;
    int incl = v;
    #pragma unroll
    for (int o = 1; o < 32; o <<= 1) {
        int u = __shfl_up_sync(0xffffffffu, incl, o);
        if (lane >= o) incl += u;
    }
    if (t == 31) w0tot = incl;
    __syncthreads();
    int excl = incl - v + ((t >= 32) ? w0tot : 0);
    if (t < SCAN_BLK) g_psum[t] = excl;
    if (t == SCAN_BLK - 1) g_rowptr[N_NODES] = v;
}

__global__ void k_scatter(const int* __restrict__ ei, const float* __restrict__ ea) {
    int e = blockIdx.x * blockDim.x + threadIdx.x;
    if (e < N_EDGES) {
        int dst = ei[N_EDGES + e];
        int base = g_rowptr[dst] + g_psum[dst >> 10];
        int pos = base + atomicAdd(&g_fill[dst], 1);
        g_edge[pos] = ((ull)__float_as_uint(ea[e]) << 32) | (unsigned)ei[e];
    }
}

// ---------------- input GEMM -------------------------------------------------
__global__ void k_ingemm(const float* __restrict__ x,
                         const float* __restrict__ Win,
                         const float* __restrict__ b_in) {
    __shared__ __align__(16) float xs[64 * 52];
    int t = threadIdx.x;
    int c = t & 63, rg = t >> 6;
    ull w2[26];
    #pragma unroll
    for (int k = 0; k < 25; k++)
        w2[k] = packf2(Win[(2 * k) * HID + c], Win[(2 * k + 1) * HID + c]);
    w2[25] = 0ull;
    int n0 = blockIdx.x * 64;
    for (int idx = t; idx < 64 * IN_DIM; idx += 256) {
        int r = idx / IN_DIM, k = idx % IN_DIM;
        int row = n0 + r;
        xs[r * 52 + k] = (row < N_NODES) ? x[row * IN_DIM + k] : 0.f;
    }
    if (rg == 0) { xs[c * 52 + 50] = 0.f; xs[c * 52 + 51] = 0.f; }
    __syncthreads();
    float bias = b_in[c];
    int rend = min(rg * 16 + 16, N_NODES - n0);
    for (int r = rg * 16; r < rend; r++) {
        const ulonglong2* hr = (const ulonglong2*)&xs[r * 52];
        ull acc_a = packf2(bias, 0.f), acc_b = 0ull;
        #pragma unroll
        for (int kk = 0; kk < 13; kk++) {
            ulonglong2 hv = hr[kk];
            acc_a = ff2(w2[2 * kk + 0], hv.x, acc_a);
            acc_b = ff2(w2[2 * kk + 1], hv.y, acc_b);
        }
        float acc = sum2(acc_a) + sum2(acc_b);
        g_h[(n0 + r) * HID + c] = acc;
        g_hh[(n0 + r) * HID + c] = __float2half_rn(acc);
    }
}

// ---------------- q/k/v/skip GEMM: HMMA, persistent 2 tiles/block ------------
__global__ __launch_bounds__(512) void k_gemm4(int li,
                        const float* __restrict__ bq, const float* __restrict__ bk,
                        const float* __restrict__ bv, const float* __restrict__ bsk) {
    __shared__ __half As[64][72];
    __shared__ __half Bs[4][64][72];
    __shared__ float  bias_s[4][64];

    int t = threadIdx.x;
    int w = t >> 5, lane = t & 31;
    int mat = w & 3, rg = w >> 2;

    const float* b;
    if (mat == 0)      b = bq  + li * 64;
    else if (mat == 1) b = bk  + li * 64;
    else if (mat == 2) b = bv  + li * 64;
    else               b = bsk + li * 64;
    float scal = (mat == 0) ? INV_SQRT_C : 1.f;

    {
        const uint4* src = (const uint4*)(g_wt + (li * 4 + mat) * 64 * 72);
        uint4* dst = (uint4*)&Bs[mat][0][0];
        for (int idx = rg * 32 + lane; idx < 576; idx += 128)
            dst[idx] = src[idx];
        if (rg == 0)
            for (int c = lane; c < 64; c += 32) bias_s[mat][c] = b[c] * scal;
    }

    int g = lane >> 2, tig = lane & 3;
    int r0 = rg * 16;
    int arow = t >> 3, acol = (t & 7) * 8;

    for (int tile = blockIdx.x; tile < NTILES; tile += gridDim.x) {
        int n0 = tile * 64;
        __syncthreads();
        {
            int row = n0 + arow;
            uint4 v = make_uint4(0u, 0u, 0u, 0u);
            if (row < N_NODES) v = *(const uint4*)&g_hh[row * 64 + acol];
            *(uint4*)&As[arow][acol] = v;
        }
        __syncthreads();

        unsigned afr[4][4];
        #pragma unroll
        for (int ks = 0; ks < 4; ks++) {
            int k0 = ks * 16;
            afr[ks][0] = *(const unsigned*)&As[r0 + g][k0 + 2 * tig];
            afr[ks][1] = *(const unsigned*)&As[r0 + g + 8][k0 + 2 * tig];
            afr[ks][2] = *(const unsigned*)&As[r0 + g][k0 + 2 * tig + 8];
            afr[ks][3] = *(const unsigned*)&As[r0 + g + 8][k0 + 2 * tig + 8];
        }

        int row0 = n0 + r0 + g;
        int row1 = row0 + 8;

        #pragma unroll
        for (int nt = 0; nt < 8; nt++) {
            int col = nt * 8 + 2 * tig;
            float c0 = bias_s[mat][col], c1 = bias_s[mat][col + 1];
            float c2 = c0, c3 = c1;
            #pragma unroll
            for (int ks = 0; ks < 4; ks++) {
                unsigned b0 = *(const unsigned*)&Bs[mat][nt * 8 + g][ks * 16 + 2 * tig];
                unsigned b1 = *(const unsigned*)&Bs[mat][nt * 8 + g][ks * 16 + 2 * tig + 8];
                asm volatile(
                    "mma.sync.aligned.m16n8k16.row.col.f32.f16.f16.f32 "
                    "{%0,%1,%2,%3}, {%4,%5,%6,%7}, {%8,%9}, {%0,%1,%2,%3};"
                    : "+f"(c0), "+f"(c1), "+f"(c2), "+f"(c3)
                    : "r"(afr[ks][0]), "r"(afr[ks][1]), "r"(afr[ks][2]), "r"(afr[ks][3]),
                      "r"(b0), "r"(b1));
            }
            if (mat == 0) {
                if (row0 < N_NODES) *(float2*)&g_q[row0 * 64 + col] = make_float2(c0, c1);
                if (row1 < N_NODES) *(float2*)&g_q[row1 * 64 + col] = make_float2(c2, c3);
            } else if (mat == 3) {
                if (row0 < N_NODES) *(float2*)&g_skip[row0 * 64 + col] = make_float2(c0, c1);
                if (row1 < N_NODES) *(float2*)&g_skip[row1 * 64 + col] = make_float2(c2, c3);
            } else {
                // interleaved kv: channels (col,col+1) -> halves (col>>1)*4 + {0,1} (k) / {2,3} (v)
                int pos = ((col >> 1) << 2) + ((mat == 2) ? 2 : 0);
                if (row0 < N_NODES) *(__half2*)&g_kv[row0 * 128 + pos] = __floats2half2_rn(c0, c1);
                if (row1 < N_NODES) *(__half2*)&g_kv[row1 * 128 + pos] = __floats2half2_rn(c2, c3);
            }
        }
    }
}

// ---------------- fused node kernel: warp/node, interleaved kv ---------------
// lane L owns channels {2L, 2L+1}; head h = L>>3 (8 lanes per head)
#define LDKV(E) __ldg((const uint2*)g_kv + (((E) & 0xffffffffu) * 32 + lane))
#define NODE_BODY(E, R) { \
    float w_ = __uint_as_float((unsigned)((E) >> 32)); \
    float2 kf_ = __half22float2(*(const __half2*)&(R).x); \
    float2 vf_ = __half22float2(*(const __half2*)&(R).y); \
    float p_ = q2.x * kf_.x + q2.y * kf_.y; \
    p_ += __shfl_xor_sync(0xffffffffu, p_, 1, 8); \
    p_ += __shfl_xor_sync(0xffffffffu, p_, 2, 8); \
    p_ += __shfl_xor_sync(0xffffffffu, p_, 4, 8); \
    float ex_ = __expf(fmaf(w_, qwe, p_)); \
    d += ex_; spw = fmaf(ex_, w_, spw); \
    accx = fmaf(ex_, vf_.x, accx); accy = fmaf(ex_, vf_.y, accy); \
}

__global__ void k_node3(int li,
                        const float* __restrict__ Wedge,
                        const float* __restrict__ Wbeta,
                        const float* __restrict__ lng,
                        const float* __restrict__ lnb) {
    int n = blockIdx.x * (blockDim.x >> 5) + (threadIdx.x >> 5);
    if (n >= N_NODES) return;
    int lane = threadIdx.x & 31;

    float2 q2  = ((const float2*)g_q)[n * 32 + lane];     // pre-scaled
    float2 we2 = ((const float2*)Wedge)[li * 32 + lane];

    // per-head dot(q, we): width-8 butterfly (all lanes get their head's sum)
    float pw = q2.x * we2.x + q2.y * we2.y;
    pw += __shfl_xor_sync(0xffffffffu, pw, 1, 8);
    pw += __shfl_xor_sync(0xffffffffu, pw, 2, 8);
    pw += __shfl_xor_sync(0xffffffffu, pw, 4, 8);
    float qwe = pw;

    int j0 = g_rowptr[n] + g_psum[n >> 10];
    int j1 = g_rowptr[n + 1] + g_psum[(n + 1) >> 10];
    int cnt = j1 - j0;
    const ull* ep = g_edge + j0;

    float d = 0.f, spw = 0.f, accx = 0.f, accy = 0.f;

    ull e0 = 0, e1 = 0, e2 = 0, e3 = 0;
    uint2 r0 = make_uint2(0u,0u), r1 = r0, r2 = r0, r3 = r0;
    if (cnt > 0) { e0 = __ldg(ep + 0); r0 = LDKV(e0); }
    if (cnt > 1) { e1 = __ldg(ep + 1); r1 = LDKV(e1); }
    if (cnt > 2) { e2 = __ldg(ep + 2); r2 = LDKV(e2); }
    if (cnt > 3) { e3 = __ldg(ep + 3); r3 = LDKV(e3); }

    int j = 0;
    for (; j + 8 <= cnt; j += 4) {
        NODE_BODY(e0, r0); e0 = __ldg(ep + j + 4); r0 = LDKV(e0);
        NODE_BODY(e1, r1); e1 = __ldg(ep + j + 5); r1 = LDKV(e1);
        NODE_BODY(e2, r2); e2 = __ldg(ep + j + 6); r2 = LDKV(e2);
        NODE_BODY(e3, r3); e3 = __ldg(ep + j + 7); r3 = LDKV(e3);
    }
    int left = cnt - j;
    if (left > 0) NODE_BODY(e0, r0);
    if (left > 1) NODE_BODY(e1, r1);
    if (left > 2) NODE_BODY(e2, r2);
    if (left > 3) NODE_BODY(e3, r3);
    for (int jj = j + 4; jj < cnt; jj++) {
        ull e = __ldg(ep + jj); uint2 r = LDKV(e);
        NODE_BODY(e, r);
    }

    // epilogue: all 32 lanes, 2 channels each
    float inv = 1.f / (d + 1e-16f);
    float ox = (accx + we2.x * spw) * inv;
    float oy = (accy + we2.y * spw) * inv;

    float2 xr = ((const float2*)g_skip)[n * 32 + lane];
    const float2* Wb = (const float2*)(Wbeta + li * 192);
    float2 w1 = Wb[lane], w2 = Wb[32 + lane], w3 = Wb[64 + lane];
    float contrib = ox * w1.x + oy * w1.y + xr.x * w2.x + xr.y * w2.y
                  + (ox - xr.x) * w3.x + (oy - xr.y) * w3.y;
    #pragma unroll
    for (int o = 16; o >= 1; o >>= 1)
        contrib += __shfl_xor_sync(0xffffffffu, contrib, o);
    float beta = 1.f / (1.f + __expf(-contrib));

    float2 hres = ((const float2*)g_h)[n * 32 + lane];
    float zx = fmaf(beta, xr.x - ox, ox) + hres.x;
    float zy = fmaf(beta, xr.y - oy, oy) + hres.y;

    float s1 = zx + zy;
    float s2 = zx * zx + zy * zy;
    #pragma unroll
    for (int o = 16; o >= 1; o >>= 1) {
        s1 += __shfl_xor_sync(0xffffffffu, s1, o);
        s2 += __shfl_xor_sync(0xffffffffu, s2, o);
    }
    float mu  = s1 * (1.f / 64.f);
    float var = s2 * (1.f / 64.f) - mu * mu;
    float rstd = rsqrtf(var + LN_EPS);
    float2 g = ((const float2*)lng)[li * 32 + lane];
    float2 b = ((const float2*)lnb)[li * 32 + lane];
    float hx = (zx - mu) * rstd * g.x + b.x;
    float hy = (zy - mu) * rstd * g.y + b.y;
    ((float2*)g_h)[n * 32 + lane] = make_float2(hx, hy);
    __half2 hh = __floats2half2_rn(hx, hy);
    ((unsigned*)g_hh)[n * 32 + lane] = *(unsigned*)&hh;
}

// ---------------- head: stage1 HMMA + stage2 FFMA2 ---------------------------
__global__ __launch_bounds__(256) void k_final(const float* __restrict__ bc1,
                        const float* __restrict__ Wc2, const float* __restrict__ bc2,
                        float* __restrict__ out) {
    __shared__ __half As[64][72];
    __shared__ __half Bs[64][72];
    __shared__ __align__(16) float h1s[64 * 64];
    __shared__ float bias1[64];

    int t = threadIdx.x;
    int w = t >> 5, lane = t & 31;
    int n0 = blockIdx.x * 64;

    for (int idx = t; idx < 512; idx += 256) {
        int row = n0 + (idx >> 3), col = (idx & 7) * 8;
        uint4 v = make_uint4(0u, 0u, 0u, 0u);
        if (row < N_NODES) v = *(const uint4*)&g_hh[row * 64 + col];
        *(uint4*)&As[idx >> 3][col] = v;
    }
    {
        const uint4* src = (const uint4*)(g_wt + 12 * 64 * 72);
        uint4* dst = (uint4*)&Bs[0][0];
        for (int idx = t; idx < 576; idx += 256) dst[idx] = src[idx];
    }
    if (t < 64) bias1[t] = bc1[t];
    __syncthreads();

    {
        int rg = w & 3, nh = w >> 2;
        int g = lane >> 2, tig = lane & 3;
        int r0 = rg * 16;
        unsigned afr[4][4];
        #pragma unroll
        for (int ks = 0; ks < 4; ks++) {
            int k0 = ks * 16;
            afr[ks][0] = *(const unsigned*)&As[r0 + g][k0 + 2 * tig];
            afr[ks][1] = *(const unsigned*)&As[r0 + g + 8][k0 + 2 * tig];
            afr[ks][2] = *(const unsigned*)&As[r0 + g][k0 + 2 * tig + 8];
            afr[ks][3] = *(const unsigned*)&As[r0 + g + 8][k0 + 2 * tig + 8];
        }
        #pragma unroll
        for (int q = 0; q < 4; q++) {
            int nt = nh * 4 + q;
            int col = nt * 8 + 2 * tig;
            float c0 = bias1[col], c1 = bias1[col + 1];
            float c2 = c0, c3 = c1;
            #pragma unroll
            for (int ks = 0; ks < 4; ks++) {
                unsigned b0 = *(const unsigned*)&Bs[nt * 8 + g][ks * 16 + 2 * tig];
                unsigned b1 = *(const unsigned*)&Bs[nt * 8 + g][ks * 16 + 2 * tig + 8];
                asm volatile(
                    "mma.sync.aligned.m16n8k16.row.col.f32.f16.f16.f32 "
                    "{%0,%1,%2,%3}, {%4,%5,%6,%7}, {%8,%9}, {%0,%1,%2,%3};"
                    : "+f"(c0), "+f"(c1), "+f"(c2), "+f"(c3)
                    : "r"(afr[ks][0]), "r"(afr[ks][1]), "r"(afr[ks][2]), "r"(afr[ks][3]),
                      "r"(b0), "r"(b1));
            }
            *(float2*)&h1s[(r0 + g) * 64 + col]     = make_float2(fmaxf(c0, 0.f), fmaxf(c1, 0.f));
            *(float2*)&h1s[(r0 + g + 8) * 64 + col] = make_float2(fmaxf(c2, 0.f), fmaxf(c3, 0.f));
        }
    }
    __syncthreads();

    if (t < 240) {
        int c2 = t % 12, rg2 = t / 12;
        ull wr2[32];
        #pragma unroll
        for (int k = 0; k < 32; k++)
            wr2[k] = packf2(Wc2[(2 * k) * NC + c2], Wc2[(2 * k + 1) * NC + c2]);
        float b2 = bc2[c2];
        int rmax = min(64, N_NODES - n0);
        for (int r = rg2; r < rmax; r += 20) {
            const ulonglong2* hr = (const ulonglong2*)&h1s[r * 64];
            ull acc_a = packf2(b2, 0.f), acc_b = 0ull;
            #pragma unroll
            for (int kk = 0; kk < 16; kk++) {
                ulonglong2 hv = hr[kk];
                acc_a = ff2(wr2[2 * kk + 0], hv.x, acc_a);
                acc_b = ff2(wr2[2 * kk + 1], hv.y, acc_b);
            }
            out[(n0 + r) * NC + c2] = sum2(acc_a) + sum2(acc_b);
        }
    }
}

// ---------------- launch -----------------------------------------------------
extern "C" void kernel_launch(void* const* d_in, const int* in_sizes, int n_in,
                              void* d_out, int out_size) {
    const float* x     = (const float*)d_in[0];
    const int*   ei    = (const int*)  d_in[1];
    const float* ea    = (const float*)d_in[2];
    const float* Win   = (const float*)d_in[3];
    const float* b_in  = (const float*)d_in[4];
    const float* Wq    = (const float*)d_in[5];
    const float* bq    = (const float*)d_in[6];
    const float* Wk    = (const float*)d_in[7];
    const float* bk    = (const float*)d_in[8];
    const float* Wv    = (const float*)d_in[9];
    const float* bv    = (const float*)d_in[10];
    const float* Wedge = (const float*)d_in[11];
    const float* Wskip = (const float*)d_in[12];
    const float* bskip = (const float*)d_in[13];
    const float* Wbeta = (const float*)d_in[14];
    const float* ln_g  = (const float*)d_in[15];
    const float* ln_b  = (const float*)d_in[16];
    const float* Wc1   = (const float*)d_in[17];
    const float* bc1   = (const float*)d_in[18];
    const float* Wc2   = (const float*)d_in[19];
    const float* bc2   = (const float*)d_in[20];
    float* out = (float*)d_out;

    int nrb = NTILES;

    // launch #4 = k_gemm4 (ncu capture slot)
    k_ingemm<<<nrb, 256>>>(x, Win, b_in);                               // 1
    k_prep_w<<<(13 * 4096 + 255) / 256, 256>>>(Wq, Wk, Wv, Wskip, Wc1); // 2
    k_hist<<<(N_EDGES + 255) / 256, 256>>>(ei);                         // 3
    k_gemm4<<<(NTILES + 1) / 2, 512>>>(0, bq, bk, bv, bskip);           // 4 (profiled)
    k_scan1<<<SCAN_BLK, 1024>>>();                                      // 5
    k_scan2<<<1, 64>>>();                                               // 6
    k_scatter<<<(N_EDGES + 255) / 256, 256>>>(ei, ea);                  // 7
    k_node3<<<(N_NODES + 7) / 8, 256>>>(0, Wedge, Wbeta, ln_g, ln_b);   // 8

    for (int li = 1; li < NLAYERS; li++) {
        k_gemm4<<<(NTILES + 1) / 2, 512>>>(li, bq, bk, bv, bskip);
        k_node3<<<(N_NODES + 7) / 8, 256>>>(li, Wedge, Wbeta, ln_g, ln_b);
    }

    k_final<<<nrb, 256>>>(bc1, Wc2, bc2, out);
}

// round 11
// speedup vs baseline: 1.6942x; 1.0765x over previous
#include <cuda_runtime.h>
#include <cuda_fp16.h>
#include <math.h>

#define N_NODES 50000
#define N_EDGES 800000
#define IN_DIM 50
#define HID 64
#define HEADS 4
#define NLAYERS 3
#define NC 12
#define INV_SQRT_C 0.25f
#define LN_EPS 1e-5f
#define SCAN_BLK ((N_NODES + 1023) / 1024)   // 49
#define NTILES ((N_NODES + 63) / 64)         // 782
#define G4_BLOCKS ((NTILES + 1) / 2)         // 391
#define PREPW_BLK ((13 * 4096 + 255) / 256)  // 208
#define HIST_BLK ((N_EDGES + 255) / 256)     // 3125
#define SCAT_BLK ((N_EDGES + 511) / 512)     // 1563

typedef unsigned long long ull;

__device__ __forceinline__ ull ff2(ull a, ull b, ull c) {
    ull d;
    asm("fma.rn.f32x2 %0, %1, %2, %3;" : "=l"(d) : "l"(a), "l"(b), "l"(c));
    return d;
}
__device__ __forceinline__ ull packf2(float lo, float hi) {
    return ((ull)__float_as_uint(hi) << 32) | (ull)__float_as_uint(lo);
}
__device__ __forceinline__ float sum2(ull v) {
    return __uint_as_float((unsigned)(v & 0xffffffffu)) + __uint_as_float((unsigned)(v >> 32));
}

// ---------------- scratch ----------------------------------------------------
__device__ __align__(16) float  g_h[N_NODES * HID];
__device__ __align__(16) __half g_hh[N_NODES * HID];
__device__ __align__(16) float  g_q[N_NODES * HID];
__device__ __align__(16) float  g_skip[N_NODES * HID];
__device__ __align__(16) __half g_kv[N_NODES * 128];   // interleaved {k2L,k2L+1,v2L,v2L+1}
__device__ __align__(16) __half g_wt[13 * 64 * 72];
__device__ int   g_cnt[N_NODES];
__device__ int   g_rowptr[N_NODES + 1];
__device__ int   g_fill[N_NODES];
__device__ ull   g_edge[N_EDGES];
__device__ int   g_psum[64];
__device__ int   g_scan_ctr;

// ================= device bodies =============================================

__device__ __forceinline__ void ingemm_body(int bid, int t,
                         const float* __restrict__ x,
                         const float* __restrict__ Win,
                         const float* __restrict__ b_in,
                         float* xs /* [64*52] smem */) {
    int c = t & 63, rg = t >> 6;
    ull w2[26];
    #pragma unroll
    for (int k = 0; k < 25; k++)
        w2[k] = packf2(Win[(2 * k) * HID + c], Win[(2 * k + 1) * HID + c]);
    w2[25] = 0ull;
    int n0 = bid * 64;
    for (int idx = t; idx < 64 * IN_DIM; idx += 256) {
        int r = idx / IN_DIM, k = idx % IN_DIM;
        int row = n0 + r;
        xs[r * 52 + k] = (row < N_NODES) ? x[row * IN_DIM + k] : 0.f;
    }
    if (rg == 0) { xs[c * 52 + 50] = 0.f; xs[c * 52 + 51] = 0.f; }
    __syncthreads();
    float bias = b_in[c];
    int rend = min(rg * 16 + 16, N_NODES - n0);
    for (int r = rg * 16; r < rend; r++) {
        const ulonglong2* hr = (const ulonglong2*)&xs[r * 52];
        ull acc_a = packf2(bias, 0.f), acc_b = 0ull;
        #pragma unroll
        for (int kk = 0; kk < 13; kk++) {
            ulonglong2 hv = hr[kk];
            acc_a = ff2(w2[2 * kk + 0], hv.x, acc_a);
            acc_b = ff2(w2[2 * kk + 1], hv.y, acc_b);
        }
        float acc = sum2(acc_a) + sum2(acc_b);
        g_h[(n0 + r) * HID + c] = acc;
        g_hh[(n0 + r) * HID + c] = __float2half_rn(acc);
    }
}

__device__ __forceinline__ void prepw_body(int id,
                         const float* __restrict__ Wq, const float* __restrict__ Wk,
                         const float* __restrict__ Wv, const float* __restrict__ Wsk,
                         const float* __restrict__ Wc1) {
    if (id >= 13 * 4096) return;
    int k = id & 63, n = (id >> 6) & 63, m = id >> 12;
    const float* W;
    float scal = 1.f;
    if (m == 12) W = Wc1;
    else {
        int li = m >> 2, mat = m & 3;
        if (mat == 0)      { W = Wq + li * 4096; scal = INV_SQRT_C; }
        else if (mat == 1) W = Wk  + li * 4096;
        else if (mat == 2) W = Wv  + li * 4096;
        else               W = Wsk + li * 4096;
    }
    g_wt[(m * 64 + n) * 72 + k] = __float2half_rn(W[k * 64 + n] * scal);
}

// gemm4 body: 512 threads, persistent over tiles {start, start+stride, ...}
__device__ __forceinline__ void gemm4_body(int li, int t, int tile_start, int tile_stride,
                        const float* __restrict__ bq, const float* __restrict__ bk,
                        const float* __restrict__ bv, const float* __restrict__ bsk) {
    __shared__ __half As[64][72];
    __shared__ __half Bs[4][64][72];
    __shared__ float  bias_s[4][64];

    int w = t >> 5, lane = t & 31;
    int mat = w & 3, rg = w >> 2;

    const float* b;
    if (mat == 0)      b = bq  + li * 64;
    else if (mat == 1) b = bk  + li * 64;
    else if (mat == 2) b = bv  + li * 64;
    else               b = bsk + li * 64;
    float scal = (mat == 0) ? INV_SQRT_C : 1.f;

    {
        const uint4* src = (const uint4*)(g_wt + (li * 4 + mat) * 64 * 72);
        uint4* dst = (uint4*)&Bs[mat][0][0];
        for (int idx = rg * 32 + lane; idx < 576; idx += 128)
            dst[idx] = src[idx];
        if (rg == 0)
            for (int c = lane; c < 64; c += 32) bias_s[mat][c] = b[c] * scal;
    }

    int g = lane >> 2, tig = lane & 3;
    int r0 = rg * 16;
    int arow = t >> 3, acol = (t & 7) * 8;

    for (int tile = tile_start; tile < NTILES; tile += tile_stride) {
        int n0 = tile * 64;
        __syncthreads();
        {
            int row = n0 + arow;
            uint4 v = make_uint4(0u, 0u, 0u, 0u);
            if (row < N_NODES) v = *(const uint4*)&g_hh[row * 64 + acol];
            *(uint4*)&As[arow][acol] = v;
        }
        __syncthreads();

        unsigned afr[4][4];
        #pragma unroll
        for (int ks = 0; ks < 4; ks++) {
            int k0 = ks * 16;
            afr[ks][0] = *(const unsigned*)&As[r0 + g][k0 + 2 * tig];
            afr[ks][1] = *(const unsigned*)&As[r0 + g + 8][k0 + 2 * tig];
            afr[ks][2] = *(const unsigned*)&As[r0 + g][k0 + 2 * tig + 8];
            afr[ks][3] = *(const unsigned*)&As[r0 + g + 8][k0 + 2 * tig + 8];
        }

        int row0 = n0 + r0 + g;
        int row1 = row0 + 8;

        #pragma unroll
        for (int nt = 0; nt < 8; nt++) {
            int col = nt * 8 + 2 * tig;
            float c0 = bias_s[mat][col], c1 = bias_s[mat][col + 1];
            float c2 = c0, c3 = c1;
            #pragma unroll
            for (int ks = 0; ks < 4; ks++) {
                unsigned b0 = *(const unsigned*)&Bs[mat][nt * 8 + g][ks * 16 + 2 * tig];
                unsigned b1 = *(const unsigned*)&Bs[mat][nt * 8 + g][ks * 16 + 2 * tig + 8];
                asm volatile(
                    "mma.sync.aligned.m16n8k16.row.col.f32.f16.f16.f32 "
                    "{%0,%1,%2,%3}, {%4,%5,%6,%7}, {%8,%9}, {%0,%1,%2,%3};"
                    : "+f"(c0), "+f"(c1), "+f"(c2), "+f"(c3)
                    : "r"(afr[ks][0]), "r"(afr[ks][1]), "r"(afr[ks][2]), "r"(afr[ks][3]),
                      "r"(b0), "r"(b1));
            }
            if (mat == 0) {
                if (row0 < N_NODES) *(float2*)&g_q[row0 * 64 + col] = make_float2(c0, c1);
                if (row1 < N_NODES) *(float2*)&g_q[row1 * 64 + col] = make_float2(c2, c3);
            } else if (mat == 3) {
                if (row0 < N_NODES) *(float2*)&g_skip[row0 * 64 + col] = make_float2(c0, c1);
                if (row1 < N_NODES) *(float2*)&g_skip[row1 * 64 + col] = make_float2(c2, c3);
            } else {
                int pos = ((col >> 1) << 2) + ((mat == 2) ? 2 : 0);
                if (row0 < N_NODES) *(__half2*)&g_kv[row0 * 128 + pos] = __floats2half2_rn(c0, c1);
                if (row1 < N_NODES) *(__half2*)&g_kv[row1 * 128 + pos] = __floats2half2_rn(c2, c3);
            }
        }
    }
}

__device__ __forceinline__ void scatter_body(int e, const int* __restrict__ ei,
                                             const float* __restrict__ ea) {
    if (e < N_EDGES) {
        int dst = ei[N_EDGES + e];
        int base = g_rowptr[dst] + g_psum[dst >> 10];
        int pos = base + atomicAdd(&g_fill[dst], 1);
        g_edge[pos] = ((ull)__float_as_uint(ea[e]) << 32) | (unsigned)ei[e];
    }
}

// ================= kernels ===================================================

// K1: ingemm | prep_w | hist (independent work, partitioned by blockIdx)
__global__ __launch_bounds__(256) void k_fused1(
        const float* __restrict__ x, const float* __restrict__ Win,
        const float* __restrict__ b_in,
        const float* __restrict__ Wq, const float* __restrict__ Wk,
        const float* __restrict__ Wv, const float* __restrict__ Wsk,
        const float* __restrict__ Wc1,
        const int* __restrict__ ei) {
    __shared__ __align__(16) float xs[64 * 52];
    int b = blockIdx.x, t = threadIdx.x;
    if (b < NTILES) {
        ingemm_body(b, t, x, Win, b_in, xs);
    } else if (b < NTILES + PREPW_BLK) {
        prepw_body((b - NTILES) * 256 + t, Wq, Wk, Wv, Wsk, Wc1);
    } else {
        int e = (b - NTILES - PREPW_BLK) * 256 + t;
        if (e < N_NODES) g_fill[e] = 0;
        if (e < N_EDGES) atomicAdd(&g_cnt[ei[N_EDGES + e]], 1);
    }
}

// K2: scan1 + (last block) scan2, counter reset
__global__ void k_scan() {
    __shared__ int wsum[32];
    __shared__ int s_last;
    __shared__ int w0tot;
    int t = threadIdx.x, lane = t & 31, wid = t >> 5;
    int i = blockIdx.x * 1024 + t;
    int v = (i < N_NODES) ? g_cnt[i] : 0;
    if (i < N_NODES) g_cnt[i] = 0;
    int incl = v;
    #pragma unroll
    for (int o = 1; o < 32; o <<= 1) {
        int u = __shfl_up_sync(0xffffffffu, incl, o);
        if (lane >= o) incl += u;
    }
    if (lane == 31) wsum[wid] = incl;
    __syncthreads();
    if (wid == 0) {
        int ws = wsum[lane];
        int wincl = ws;
        #pragma unroll
        for (int o = 1; o < 32; o <<= 1) {
            int u = __shfl_up_sync(0xffffffffu, wincl, o);
            if (lane >= o) wincl += u;
        }
        wsum[lane] = wincl - ws;
        if (lane == 31) g_psum[blockIdx.x] = wincl;
    }
    __syncthreads();
    int excl = incl - v + wsum[wid];
    if (i < N_NODES) g_rowptr[i] = excl;

    // elect last-finishing block to scan the 49 block sums
    __threadfence();
    if (t == 0) s_last = (atomicAdd(&g_scan_ctr, 1) == SCAN_BLK - 1) ? 1 : 0;
    __syncthreads();
    if (s_last) {
        int v2 = (t < SCAN_BLK) ? *((volatile int*)g_psum + t) : 0;
        int incl2 = v2;
        if (t < 64) {
            #pragma unroll
            for (int o = 1; o < 32; o <<= 1) {
                int u = __shfl_up_sync(0xffffffffu, incl2, o);
                if (lane >= o) incl2 += u;
            }
            if (t == 31) w0tot = incl2;
        }
        __syncthreads();
        if (t < 64) {
            int excl2 = incl2 - v2 + ((t >= 32) ? w0tot : 0);
            if (t < SCAN_BLK) g_psum[t] = excl2;
            if (t == SCAN_BLK - 1) g_rowptr[N_NODES] = v2;
        }
        if (t == 0) g_scan_ctr = 0;   // reset for next replay
    }
}

// K3: gemm4(li) | scatter (independent)
__global__ __launch_bounds__(512) void k_gemm4sc(int li,
                        const float* __restrict__ bq, const float* __restrict__ bk,
                        const float* __restrict__ bv, const float* __restrict__ bsk,
                        const int* __restrict__ ei, const float* __restrict__ ea) {
    if (blockIdx.x < G4_BLOCKS) {
        gemm4_body(li, threadIdx.x, blockIdx.x, G4_BLOCKS, bq, bk, bv, bsk);
    } else {
        int e = (blockIdx.x - G4_BLOCKS) * 512 + threadIdx.x;
        scatter_body(e, ei, ea);
    }
}

// plain gemm4 (layers 1,2)
__global__ __launch_bounds__(512) void k_gemm4(int li,
                        const float* __restrict__ bq, const float* __restrict__ bk,
                        const float* __restrict__ bv, const float* __restrict__ bsk) {
    gemm4_body(li, threadIdx.x, blockIdx.x, G4_BLOCKS, bq, bk, bv, bsk);
}

// ---------------- fused node kernel (unchanged from R10) ---------------------
#define LDKV(E) __ldg((const uint2*)g_kv + (((E) & 0xffffffffu) * 32 + lane))
#define NODE_BODY(E, R) { \
    float w_ = __uint_as_float((unsigned)((E) >> 32)); \
    float2 kf_ = __half22float2(*(const __half2*)&(R).x); \
    float2 vf_ = __half22float2(*(const __half2*)&(R).y); \
    float p_ = q2.x * kf_.x + q2.y * kf_.y; \
    p_ += __shfl_xor_sync(0xffffffffu, p_, 1, 8); \
    p_ += __shfl_xor_sync(0xffffffffu, p_, 2, 8); \
    p_ += __shfl_xor_sync(0xffffffffu, p_, 4, 8); \
    float ex_ = __expf(fmaf(w_, qwe, p_)); \
    d += ex_; spw = fmaf(ex_, w_, spw); \
    accx = fmaf(ex_, vf_.x, accx); accy = fmaf(ex_, vf_.y, accy); \
}

__global__ void k_node3(int li,
                        const float* __restrict__ Wedge,
                        const float* __restrict__ Wbeta,
                        const float* __restrict__ lng,
                        const float* __restrict__ lnb) {
    int n = blockIdx.x * (blockDim.x >> 5) + (threadIdx.x >> 5);
    if (n >= N_NODES) return;
    int lane = threadIdx.x & 31;

    float2 q2  = ((const float2*)g_q)[n * 32 + lane];
    float2 we2 = ((const float2*)Wedge)[li * 32 + lane];

    float pw = q2.x * we2.x + q2.y * we2.y;
    pw += __shfl_xor_sync(0xffffffffu, pw, 1, 8);
    pw += __shfl_xor_sync(0xffffffffu, pw, 2, 8);
    pw += __shfl_xor_sync(0xffffffffu, pw, 4, 8);
    float qwe = pw;

    int j0 = g_rowptr[n] + g_psum[n >> 10];
    int j1 = g_rowptr[n + 1] + g_psum[(n + 1) >> 10];
    int cnt = j1 - j0;
    const ull* ep = g_edge + j0;

    float d = 0.f, spw = 0.f, accx = 0.f, accy = 0.f;

    ull e0 = 0, e1 = 0, e2 = 0, e3 = 0;
    uint2 r0 = make_uint2(0u,0u), r1 = r0, r2 = r0, r3 = r0;
    if (cnt > 0) { e0 = __ldg(ep + 0); r0 = LDKV(e0); }
    if (cnt > 1) { e1 = __ldg(ep + 1); r1 = LDKV(e1); }
    if (cnt > 2) { e2 = __ldg(ep + 2); r2 = LDKV(e2); }
    if (cnt > 3) { e3 = __ldg(ep + 3); r3 = LDKV(e3); }

    int j = 0;
    for (; j + 8 <= cnt; j += 4) {
        NODE_BODY(e0, r0); e0 = __ldg(ep + j + 4); r0 = LDKV(e0);
        NODE_BODY(e1, r1); e1 = __ldg(ep + j + 5); r1 = LDKV(e1);
        NODE_BODY(e2, r2); e2 = __ldg(ep + j + 6); r2 = LDKV(e2);
        NODE_BODY(e3, r3); e3 = __ldg(ep + j + 7); r3 = LDKV(e3);
    }
    int left = cnt - j;
    if (left > 0) NODE_BODY(e0, r0);
    if (left > 1) NODE_BODY(e1, r1);
    if (left > 2) NODE_BODY(e2, r2);
    if (left > 3) NODE_BODY(e3, r3);
    for (int jj = j + 4; jj < cnt; jj++) {
        ull e = __ldg(ep + jj); uint2 r = LDKV(e);
        NODE_BODY(e, r);
    }

    float inv = 1.f / (d + 1e-16f);
    float ox = (accx + we2.x * spw) * inv;
    float oy = (accy + we2.y * spw) * inv;

    float2 xr = ((const float2*)g_skip)[n * 32 + lane];
    const float2* Wb = (const float2*)(Wbeta + li * 192);
    float2 w1 = Wb[lane], w2 = Wb[32 + lane], w3 = Wb[64 + lane];
    float contrib = ox * w1.x + oy * w1.y + xr.x * w2.x + xr.y * w2.y
                  + (ox - xr.x) * w3.x + (oy - xr.y) * w3.y;
    #pragma unroll
    for (int o = 16; o >= 1; o >>= 1)
        contrib += __shfl_xor_sync(0xffffffffu, contrib, o);
    float beta = 1.f / (1.f + __expf(-contrib));

    float2 hres = ((const float2*)g_h)[n * 32 + lane];
    float zx = fmaf(beta, xr.x - ox, ox) + hres.x;
    float zy = fmaf(beta, xr.y - oy, oy) + hres.y;

    float s1 = zx + zy;
    float s2 = zx * zx + zy * zy;
    #pragma unroll
    for (int o = 16; o >= 1; o >>= 1) {
        s1 += __shfl_xor_sync(0xffffffffu, s1, o);
        s2 += __shfl_xor_sync(0xffffffffu, s2, o);
    }
    float mu  = s1 * (1.f / 64.f);
    float var = s2 * (1.f / 64.f) - mu * mu;
    float rstd = rsqrtf(var + LN_EPS);
    float2 g = ((const float2*)lng)[li * 32 + lane];
    float2 b = ((const float2*)lnb)[li * 32 + lane];
    float hx = (zx - mu) * rstd * g.x + b.x;
    float hy = (zy - mu) * rstd * g.y + b.y;
    ((float2*)g_h)[n * 32 + lane] = make_float2(hx, hy);
    __half2 hh = __floats2half2_rn(hx, hy);
    ((unsigned*)g_hh)[n * 32 + lane] = *(unsigned*)&hh;
}

// ---------------- head: stage1 HMMA + stage2 FFMA2 ---------------------------
__global__ __launch_bounds__(256) void k_final(const float* __restrict__ bc1,
                        const float* __restrict__ Wc2, const float* __restrict__ bc2,
                        float* __restrict__ out) {
    __shared__ __half As[64][72];
    __shared__ __half Bs[64][72];
    __shared__ __align__(16) float h1s[64 * 64];
    __shared__ float bias1[64];

    int t = threadIdx.x;
    int w = t >> 5, lane = t & 31;
    int n0 = blockIdx.x * 64;

    for (int idx = t; idx < 512; idx += 256) {
        int row = n0 + (idx >> 3), col = (idx & 7) * 8;
        uint4 v = make_uint4(0u, 0u, 0u, 0u);
        if (row < N_NODES) v = *(const uint4*)&g_hh[row * 64 + col];
        *(uint4*)&As[idx >> 3][col] = v;
    }
    {
        const uint4* src = (const uint4*)(g_wt + 12 * 64 * 72);
        uint4* dst = (uint4*)&Bs[0][0];
        for (int idx = t; idx < 576; idx += 256) dst[idx] = src[idx];
    }
    if (t < 64) bias1[t] = bc1[t];
    __syncthreads();

    {
        int rg = w & 3, nh = w >> 2;
        int g = lane >> 2, tig = lane & 3;
        int r0 = rg * 16;
        unsigned afr[4][4];
        #pragma unroll
        for (int ks = 0; ks < 4; ks++) {
            int k0 = ks * 16;
            afr[ks][0] = *(const unsigned*)&As[r0 + g][k0 + 2 * tig];
            afr[ks][1] = *(const unsigned*)&As[r0 + g + 8][k0 + 2 * tig];
            afr[ks][2] = *(const unsigned*)&As[r0 + g][k0 + 2 * tig + 8];
            afr[ks][3] = *(const unsigned*)&As[r0 + g + 8][k0 + 2 * tig + 8];
        }
        #pragma unroll
        for (int q = 0; q < 4; q++) {
            int nt = nh * 4 + q;
            int col = nt * 8 + 2 * tig;
            float c0 = bias1[col], c1 = bias1[col + 1];
            float c2 = c0, c3 = c1;
            #pragma unroll
            for (int ks = 0; ks < 4; ks++) {
                unsigned b0 = *(const unsigned*)&Bs[nt * 8 + g][ks * 16 + 2 * tig];
                unsigned b1 = *(const unsigned*)&Bs[nt * 8 + g][ks * 16 + 2 * tig + 8];
                asm volatile(
                    "mma.sync.aligned.m16n8k16.row.col.f32.f16.f16.f32 "
                    "{%0,%1,%2,%3}, {%4,%5,%6,%7}, {%8,%9}, {%0,%1,%2,%3};"
                    : "+f"(c0), "+f"(c1), "+f"(c2), "+f"(c3)
                    : "r"(afr[ks][0]), "r"(afr[ks][1]), "r"(afr[ks][2]), "r"(afr[ks][3]),
                      "r"(b0), "r"(b1));
            }
            *(float2*)&h1s[(r0 + g) * 64 + col]     = make_float2(fmaxf(c0, 0.f), fmaxf(c1, 0.f));
            *(float2*)&h1s[(r0 + g + 8) * 64 + col] = make_float2(fmaxf(c2, 0.f), fmaxf(c3, 0.f));
        }
    }
    __syncthreads();

    if (t < 240) {
        int c2 = t % 12, rg2 = t / 12;
        ull wr2[32];
        #pragma unroll
        for (int k = 0; k < 32; k++)
            wr2[k] = packf2(Wc2[(2 * k) * NC + c2], Wc2[(2 * k + 1) * NC + c2]);
        float b2 = bc2[c2];
        int rmax = min(64, N_NODES - n0);
        for (int r = rg2; r < rmax; r += 20) {
            const ulonglong2* hr = (const ulonglong2*)&h1s[r * 64];
            ull acc_a = packf2(b2, 0.f), acc_b = 0ull;
            #pragma unroll
            for (int kk = 0; kk < 16; kk++) {
                ulonglong2 hv = hr[kk];
                acc_a = ff2(wr2[2 * kk + 0], hv.x, acc_a);
                acc_b = ff2(wr2[2 * kk + 1], hv.y, acc_b);
            }
            out[(n0 + r) * NC + c2] = sum2(acc_a) + sum2(acc_b);
        }
    }
}

// ---------------- launch -----------------------------------------------------
extern "C" void kernel_launch(void* const* d_in, const int* in_sizes, int n_in,
                              void* d_out, int out_size) {
    const float* x     = (const float*)d_in[0];
    const int*   ei    = (const int*)  d_in[1];
    const float* ea    = (const float*)d_in[2];
    const float* Win   = (const float*)d_in[3];
    const float* b_in  = (const float*)d_in[4];
    const float* Wq    = (const float*)d_in[5];
    const float* bq    = (const float*)d_in[6];
    const float* Wk    = (const float*)d_in[7];
    const float* bk    = (const float*)d_in[8];
    const float* Wv    = (const float*)d_in[9];
    const float* bv    = (const float*)d_in[10];
    const float* Wedge = (const float*)d_in[11];
    const float* Wskip = (const float*)d_in[12];
    const float* bskip = (const float*)d_in[13];
    const float* Wbeta = (const float*)d_in[14];
    const float* ln_g  = (const float*)d_in[15];
    const float* ln_b  = (const float*)d_in[16];
    const float* Wc1   = (const float*)d_in[17];
    const float* bc1   = (const float*)d_in[18];
    const float* Wc2   = (const float*)d_in[19];
    const float* bc2   = (const float*)d_in[20];
    float* out = (float*)d_out;

    // launch #4 (ncu capture slot) = k_node3 layer 0
    k_fused1<<<NTILES + PREPW_BLK + HIST_BLK, 256>>>(x, Win, b_in,
                Wq, Wk, Wv, Wskip, Wc1, ei);                             // 1
    k_scan<<<SCAN_BLK, 1024>>>();                                        // 2
    k_gemm4sc<<<G4_BLOCKS + SCAT_BLK, 512>>>(0, bq, bk, bv, bskip, ei, ea); // 3
    k_node3<<<(N_NODES + 7) / 8, 256>>>(0, Wedge, Wbeta, ln_g, ln_b);    // 4 (profiled)

    for (int li = 1; li < NLAYERS; li++) {
        k_gemm4<<<G4_BLOCKS, 512>>>(li, bq, bk, bv, bskip);
        k_node3<<<(N_NODES + 7) / 8, 256>>>(li, Wedge, Wbeta, ln_g, ln_b);
    }

    k_final<<<NTILES, 256>>>(bc1, Wc2, bc2, out);
}